// round 10
// baseline (speedup 1.0000x reference)
#include <cuda_runtime.h>
#include <cuda_bf16.h>
#include <cstdint>

// Problem constants
#define N_NODES 4096
#define F_IN    256
#define F_OUT   256
#define H_HEADS 4
#define D_HEAD  64
#define C_OUT   256

#define JSPLIT  4
#define JRANGE  (N_NODES / JSPLIT)   // 1024 per CTA

// ---------------- scratch (no cudaMalloc allowed) ----------------
__device__ __align__(16) float g_h  [N_NODES * F_OUT];
__device__ __align__(16) float g_S  [N_NODES * H_HEADS];      // [n*4+h]
__device__ __align__(16) float g_F1 [N_NODES * H_HEADS];
__device__ __align__(16) float g_F2 [N_NODES * H_HEADS];
__device__ __align__(16) float g_Tt [H_HEADS * N_NODES];      // [h][n]
__device__ __align__(16) float2 g_E12t[H_HEADS * N_NODES];    // [h][n] = {E1, E2}
// fragment-packed B: [h][j16][c8][lane] -> uint4{hi_b0, hi_b1, lo_b0, lo_b1}
__device__ uint4 g_Bpk[H_HEADS * (N_NODES / 16) * 8 * 32];
__device__ __align__(16) float g_U [JSPLIT][N_NODES * C_OUT];
__device__ __align__(16) float g_Z [JSPLIT][N_NODES * H_HEADS];

// ---------------- mma.sync helper (sm_80+ portable HMMA) ----------------
__device__ __forceinline__ void mma16816(float* c, const uint32_t* a,
                                         uint32_t b0, uint32_t b1) {
    asm volatile(
        "mma.sync.aligned.m16n8k16.row.col.f32.bf16.bf16.f32 "
        "{%0,%1,%2,%3}, {%4,%5,%6,%7}, {%8,%9}, {%0,%1,%2,%3};"
        : "+f"(c[0]), "+f"(c[1]), "+f"(c[2]), "+f"(c[3])
        : "r"(a[0]), "r"(a[1]), "r"(a[2]), "r"(a[3]), "r"(b0), "r"(b1));
}

// ================= K1: h = x @ W^T  (4096x256x256) =================
__global__ void __launch_bounds__(256) k1_gemm(const float* __restrict__ x,
                                               const float* __restrict__ W) {
    __shared__ float xs[16][68];
    __shared__ float ws[16][68];
    const int tid = threadIdx.x;
    const int m0 = blockIdx.x * 64;
    const int n0 = blockIdx.y * 64;
    const int tr = tid >> 4, tc = tid & 15;
    const int lm = tid >> 2, lk4 = (tid & 3) << 2;

    float acc[4][4];
#pragma unroll
    for (int r = 0; r < 4; r++)
#pragma unroll
        for (int c = 0; c < 4; c++) acc[r][c] = 0.f;

    for (int k0 = 0; k0 < F_IN; k0 += 16) {
        float4 xv = *(const float4*)(x + (size_t)(m0 + lm) * F_IN + k0 + lk4);
        float4 wv = *(const float4*)(W + (size_t)(n0 + lm) * F_IN + k0 + lk4);
        __syncthreads();
        xs[lk4 + 0][lm] = xv.x; xs[lk4 + 1][lm] = xv.y;
        xs[lk4 + 2][lm] = xv.z; xs[lk4 + 3][lm] = xv.w;
        ws[lk4 + 0][lm] = wv.x; ws[lk4 + 1][lm] = wv.y;
        ws[lk4 + 2][lm] = wv.z; ws[lk4 + 3][lm] = wv.w;
        __syncthreads();
#pragma unroll
        for (int kk = 0; kk < 16; kk++) {
            float xa[4], wb[4];
#pragma unroll
            for (int r = 0; r < 4; r++) xa[r] = xs[kk][tr * 4 + r];
#pragma unroll
            for (int c = 0; c < 4; c++) wb[c] = ws[kk][tc * 4 + c];
#pragma unroll
            for (int r = 0; r < 4; r++)
#pragma unroll
                for (int c = 0; c < 4; c++) acc[r][c] += xa[r] * wb[c];
        }
    }
#pragma unroll
    for (int r = 0; r < 4; r++)
        *(float4*)(g_h + (size_t)(m0 + tr * 4 + r) * F_OUT + n0 + tc * 4) =
            make_float4(acc[r][0], acc[r][1], acc[r][2], acc[r][3]);
}

// ============ K2: per-node logits + exp factor tables ============
__global__ void __launch_bounds__(256) k2_logits(const float* __restrict__ a_src,
                                                 const float* __restrict__ a_dst) {
    const int idx = blockIdx.x * 256 + threadIdx.x;
    const int n  = idx >> 2;
    const int hh = idx & 3;
    const float* hp = g_h + (size_t)n * C_OUT + hh * D_HEAD;
    const float* as = a_src + hh * D_HEAD;
    const float* ad = a_dst + hh * D_HEAD;
    float s = 0.f, t = 0.f;
#pragma unroll
    for (int d = 0; d < D_HEAD; d += 4) {
        float4 hv = *(const float4*)(hp + d);
        float4 av = *(const float4*)(as + d);
        float4 dv = *(const float4*)(ad + d);
        s += hv.x * av.x + hv.y * av.y + hv.z * av.z + hv.w * av.w;
        t += hv.x * dv.x + hv.y * dv.y + hv.z * dv.z + hv.w * dv.w;
    }
    g_S [idx] = s;
    g_F1[idx] = expf(s);
    g_F2[idx] = expf(0.2f * s);
    g_Tt  [hh * N_NODES + n] = t;
    g_E12t[hh * N_NODES + n] = make_float2(expf(t), expf(0.2f * t));
}

// ============ K2b: pack h -> fragment-order bf16 hi/lo B tiles ============
__global__ void __launch_bounds__(256) k2b_pack() {
    __shared__ float ts[32][33];
    const int tid = threadIdx.x;
    const int tx = tid & 31, ty = tid >> 5;
    const int n0 = blockIdx.x * 32;   // j dimension (nodes)
    const int c0 = blockIdx.y * 32;   // feature dimension
#pragma unroll
    for (int k = 0; k < 4; k++)
        ts[ty + 8 * k][tx] = g_h[(size_t)(n0 + ty + 8 * k) * C_OUT + c0 + tx];
    __syncthreads();

    const int lane = tid & 31;
    const int m    = lane & 3;
    const int cr   = lane >> 2;
    const int c8l  = (tid >> 5) & 3;
    const int j16l = tid >> 7;
    const int jl   = j16l * 16 + 2 * m;
    const int cl   = c8l * 8 + cr;

    const float w0 = ts[jl][cl],     w1 = ts[jl + 1][cl];
    const float w8 = ts[jl + 8][cl], w9 = ts[jl + 9][cl];
    const uint32_t u0 = __float_as_uint(w0), u1 = __float_as_uint(w1);
    const uint32_t u8 = __float_as_uint(w8), u9 = __float_as_uint(w9);
    const uint32_t xhi = (u0 >> 16) | (u1 & 0xffff0000u);
    const uint32_t yhi = (u8 >> 16) | (u9 & 0xffff0000u);
    const float l0 = w0 - __uint_as_float(u0 & 0xffff0000u);
    const float l1 = w1 - __uint_as_float(u1 & 0xffff0000u);
    const float l8 = w8 - __uint_as_float(u8 & 0xffff0000u);
    const float l9 = w9 - __uint_as_float(u9 & 0xffff0000u);
    __nv_bfloat162 p01 = __floats2bfloat162_rn(l0, l1);
    __nv_bfloat162 p89 = __floats2bfloat162_rn(l8, l9);

    const int cg  = c0 + cl;
    const int h   = cg >> 6;
    const int c8  = (cg & 63) >> 3;
    const int j16 = (n0 >> 4) + j16l;
    g_Bpk[((h * (N_NODES / 16) + j16) * 8 + c8) * 32 + lane] =
        make_uint4(xhi, yhi, *reinterpret_cast<uint32_t*>(&p01),
                   *reinterpret_cast<uint32_t*>(&p89));
}

// ---- weight for one (i, j): factored-exp masked softmax term ----
__device__ __forceinline__ float gat_w(float S, float F1, float F2,
                                       float T, float E1, float E2,
                                       float a, float& Z) {
    const float t = S + T;
    const float p = (t >= 0.f) ? F1 * E1 : F2 * E2;
    float w = 0.f;
    if (a > 0.f) { Z += p; w = a * p; }
    return w;
}

// ======= K3: fused masked-softmax + aggregation via mma.sync (HMMA) =======
// Warp tile: 32 rows x 64 cols (one head). CTA: 128 thr / 4 warps =
// 64 rows x 128 cols (2 heads). Grid: (64 i-tiles, 2 head-pairs, JSPLIT).
// 3 CTAs/SM residency target for latency hiding.
__global__ void __launch_bounds__(128, 3) k3_agg(const float* __restrict__ adj) {
    const int tid  = threadIdx.x;
    const int wid  = tid >> 5;
    const int lane = tid & 31;
    const int i0   = blockIdx.x * 64;
    const int hp   = blockIdx.y;
    const int js   = blockIdx.z;
    const int rg   = wid >> 1;                 // row group 0..1
    const int h    = hp * 2 + (wid & 1);       // head for this warp
    const int m    = lane & 3;
    const int rbase = i0 + rg * 32 + (lane >> 2);
    const int jbeg  = js * JRANGE;

    float S[4], F1[4], F2[4], Z[4];
    const float* adjp[4];
#pragma unroll
    for (int r4 = 0; r4 < 4; r4++) {
        const int idx = (rbase + r4 * 8) * H_HEADS + h;
        S[r4] = g_S[idx]; F1[r4] = g_F1[idx]; F2[r4] = g_F2[idx];
        Z[r4] = 0.f;
        adjp[r4] = adj + (size_t)(rbase + r4 * 8) * N_NODES + jbeg;
    }
    const float*  Tp  = g_Tt + h * N_NODES + jbeg;
    const float4* Ep4 = (const float4*)(g_E12t + h * N_NODES + jbeg);
    const uint4*  Bbase = g_Bpk + (size_t)(h * (N_NODES / 16) + (jbeg >> 4)) * 8 * 32 + lane;

    float acc[2][8][4];
#pragma unroll
    for (int mt = 0; mt < 2; mt++)
#pragma unroll
        for (int nt = 0; nt < 8; nt++)
#pragma unroll
            for (int q = 0; q < 4; q++) acc[mt][nt][q] = 0.f;

    const int sl0 = (lane & ~3) | (m >> 1);   // quad src lane for k0 pairs
    const int sl1 = sl0 + 2;                  // quad src lane for k0+8 pairs
    const bool odd = (m & 1);

#pragma unroll 1
    for (int jb = 0; jb < JRANGE; jb += 16) {
        // per-j tables for this lane's 4 owned j (jb+4m .. jb+4m+3)
        const float4 T4 = *(const float4*)(Tp + jb + 4 * m);
        const float4 Ea = Ep4[(jb >> 1) + 2 * m];
        const float4 Eb = Ep4[(jb >> 1) + 2 * m + 1];

        uint32_t ahi[2][4], alo[2][4];
#pragma unroll
        for (int r4 = 0; r4 < 4; r4++) {
            const float4 A4 = *(const float4*)(adjp[r4] + jb + 4 * m);
            const float w0 = gat_w(S[r4], F1[r4], F2[r4], T4.x, Ea.x, Ea.y, A4.x, Z[r4]);
            const float w1 = gat_w(S[r4], F1[r4], F2[r4], T4.y, Ea.z, Ea.w, A4.y, Z[r4]);
            const float w2 = gat_w(S[r4], F1[r4], F2[r4], T4.z, Eb.x, Eb.y, A4.z, Z[r4]);
            const float w3 = gat_w(S[r4], F1[r4], F2[r4], T4.w, Eb.z, Eb.w, A4.w, Z[r4]);
            const uint32_t u0 = __float_as_uint(w0), u1 = __float_as_uint(w1);
            const uint32_t u2 = __float_as_uint(w2), u3 = __float_as_uint(w3);
            const uint32_t whiA = (u0 >> 16) | (u1 & 0xffff0000u);  // j pair 4m
            const uint32_t whiB = (u2 >> 16) | (u3 & 0xffff0000u);  // j pair 4m+2
            const float l0 = w0 - __uint_as_float(u0 & 0xffff0000u);
            const float l1 = w1 - __uint_as_float(u1 & 0xffff0000u);
            const float l2 = w2 - __uint_as_float(u2 & 0xffff0000u);
            const float l3 = w3 - __uint_as_float(u3 & 0xffff0000u);
            __nv_bfloat162 pA = __floats2bfloat162_rn(l0, l1);
            __nv_bfloat162 pB = __floats2bfloat162_rn(l2, l3);
            const uint32_t wloA = *reinterpret_cast<const uint32_t*>(&pA);
            const uint32_t wloB = *reinterpret_cast<const uint32_t*>(&pB);

            // redistribute quad-owned pairs into fragment positions
            const uint32_t hA0 = __shfl_sync(0xffffffffu, whiA, sl0);
            const uint32_t hB0 = __shfl_sync(0xffffffffu, whiB, sl0);
            const uint32_t hA1 = __shfl_sync(0xffffffffu, whiA, sl1);
            const uint32_t hB1 = __shfl_sync(0xffffffffu, whiB, sl1);
            const uint32_t lA0 = __shfl_sync(0xffffffffu, wloA, sl0);
            const uint32_t lB0 = __shfl_sync(0xffffffffu, wloB, sl0);
            const uint32_t lA1 = __shfl_sync(0xffffffffu, wloA, sl1);
            const uint32_t lB1 = __shfl_sync(0xffffffffu, wloB, sl1);
            const int mt = r4 >> 1, hf = r4 & 1;
            ahi[mt][hf]     = odd ? hB0 : hA0;
            ahi[mt][2 + hf] = odd ? hB1 : hA1;
            alo[mt][hf]     = odd ? lB0 : lA0;
            alo[mt][2 + hf] = odd ? lB1 : lA1;
        }

        // B fragments (one coalesced LDG.128 per nt) + 3-product split MMAs
        const uint4* Bp = Bbase + (size_t)(jb >> 4) * 8 * 32;
#pragma unroll
        for (int nt = 0; nt < 8; nt++) {
            const uint4 bv = Bp[nt * 32];
#pragma unroll
            for (int mt = 0; mt < 2; mt++) {
                mma16816(acc[mt][nt], ahi[mt], bv.x, bv.y);
                mma16816(acc[mt][nt], ahi[mt], bv.z, bv.w);
                mma16816(acc[mt][nt], alo[mt], bv.x, bv.y);
            }
        }
    }

    // Z: reduce over the 4 lanes of each quad (disjoint j coverage)
#pragma unroll
    for (int r4 = 0; r4 < 4; r4++) {
        Z[r4] += __shfl_xor_sync(0xffffffffu, Z[r4], 1);
        Z[r4] += __shfl_xor_sync(0xffffffffu, Z[r4], 2);
    }
    if (m == 0) {
#pragma unroll
        for (int r4 = 0; r4 < 4; r4++)
            g_Z[js][(rbase + r4 * 8) * H_HEADS + h] = Z[r4];
    }

    // U partial store
#pragma unroll
    for (int mt = 0; mt < 2; mt++) {
        const int row_lo = i0 + rg * 32 + mt * 16 + (lane >> 2);
        const int row_hi = row_lo + 8;
#pragma unroll
        for (int nt = 0; nt < 8; nt++) {
            const int col = h * 64 + nt * 8 + 2 * m;
            *(float2*)(g_U[js] + (size_t)row_lo * C_OUT + col) =
                make_float2(acc[mt][nt][0], acc[mt][nt][1]);
            *(float2*)(g_U[js] + (size_t)row_hi * C_OUT + col) =
                make_float2(acc[mt][nt][2], acc[mt][nt][3]);
        }
    }
}

// ============ K4: reduce splits + normalize (+ nan_to_num) ============
__global__ void __launch_bounds__(256) k4_final(float* __restrict__ out) {
    const int idx = blockIdx.x * 256 + threadIdx.x;   // one float4 each
    const int n  = idx >> 6;
    const int c4 = (idx & 63) * 4;
    const int hh = c4 >> 6;
    float Z = 0.f;
#pragma unroll
    for (int s = 0; s < JSPLIT; s++) Z += g_Z[s][n * H_HEADS + hh];
    float4 u = make_float4(0.f, 0.f, 0.f, 0.f);
#pragma unroll
    for (int s = 0; s < JSPLIT; s++) {
        float4 v = *(const float4*)(g_U[s] + (size_t)n * C_OUT + c4);
        u.x += v.x; u.y += v.y; u.z += v.z; u.w += v.w;
    }
    const float r = (Z > 0.f) ? (1.f / Z) : 0.f;
    *(float4*)(out + (size_t)n * C_OUT + c4) =
        make_float4(u.x * r, u.y * r, u.z * r, u.w * r);
}

// ---------------- launch ----------------
extern "C" void kernel_launch(void* const* d_in, const int* in_sizes, int n_in,
                              void* d_out, int out_size) {
    const float* x     = (const float*)d_in[0];
    const float* adj   = (const float*)d_in[1];
    const float* W     = (const float*)d_in[2];
    const float* a_src = (const float*)d_in[3];
    const float* a_dst = (const float*)d_in[4];
    float* out = (float*)d_out;

    k1_gemm<<<dim3(N_NODES / 64, F_OUT / 64), 256>>>(x, W);
    k2_logits<<<(N_NODES * H_HEADS) / 256, 256>>>(a_src, a_dst);
    k2b_pack<<<dim3(N_NODES / 32, C_OUT / 32), 256>>>();
    k3_agg<<<dim3(N_NODES / 64, 2, JSPLIT), 128>>>(adj);
    k4_final<<<(N_NODES * C_OUT / 4) / 256, 256>>>(out);
}

// round 11
// speedup vs baseline: 1.0225x; 1.0225x over previous
#include <cuda_runtime.h>
#include <cuda_bf16.h>
#include <cstdint>

// Problem constants
#define N_NODES 4096
#define F_IN    256
#define F_OUT   256
#define H_HEADS 4
#define D_HEAD  64
#define C_OUT   256

#define JSPLIT  4
#define JRANGE  (N_NODES / JSPLIT)   // 1024 per CTA
#define NTILES  (JRANGE / 16)        // 64

// ---------------- scratch (no cudaMalloc allowed) ----------------
__device__ __align__(16) float g_h  [N_NODES * F_OUT];
__device__ __align__(16) float g_S  [N_NODES * H_HEADS];      // [n*4+h]
__device__ __align__(16) float g_F1 [N_NODES * H_HEADS];
__device__ __align__(16) float g_F2 [N_NODES * H_HEADS];
__device__ __align__(16) float g_Tt [H_HEADS * N_NODES];      // [h][n]
__device__ __align__(16) float2 g_E12t[H_HEADS * N_NODES];    // [h][n] = {E1, E2}
// fragment-packed B: [h][j16][c8][lane] -> uint4{hi_b0, hi_b1, lo_b0, lo_b1}
__device__ uint4 g_Bpk[H_HEADS * (N_NODES / 16) * 8 * 32];
__device__ __align__(16) float g_U [JSPLIT][N_NODES * C_OUT];
__device__ __align__(16) float g_Z [JSPLIT][N_NODES * H_HEADS];

// ---------------- mma.sync helper (sm_80+ portable HMMA) ----------------
__device__ __forceinline__ void mma16816(float* c, const uint32_t* a,
                                         uint32_t b0, uint32_t b1) {
    asm volatile(
        "mma.sync.aligned.m16n8k16.row.col.f32.bf16.bf16.f32 "
        "{%0,%1,%2,%3}, {%4,%5,%6,%7}, {%8,%9}, {%0,%1,%2,%3};"
        : "+f"(c[0]), "+f"(c[1]), "+f"(c[2]), "+f"(c[3])
        : "r"(a[0]), "r"(a[1]), "r"(a[2]), "r"(a[3]), "r"(b0), "r"(b1));
}

// ================= K1: h = x @ W^T  (4096x256x256) =================
__global__ void __launch_bounds__(256) k1_gemm(const float* __restrict__ x,
                                               const float* __restrict__ W) {
    __shared__ float xs[16][68];
    __shared__ float ws[16][68];
    const int tid = threadIdx.x;
    const int m0 = blockIdx.x * 64;
    const int n0 = blockIdx.y * 64;
    const int tr = tid >> 4, tc = tid & 15;
    const int lm = tid >> 2, lk4 = (tid & 3) << 2;

    float acc[4][4];
#pragma unroll
    for (int r = 0; r < 4; r++)
#pragma unroll
        for (int c = 0; c < 4; c++) acc[r][c] = 0.f;

    for (int k0 = 0; k0 < F_IN; k0 += 16) {
        float4 xv = *(const float4*)(x + (size_t)(m0 + lm) * F_IN + k0 + lk4);
        float4 wv = *(const float4*)(W + (size_t)(n0 + lm) * F_IN + k0 + lk4);
        __syncthreads();
        xs[lk4 + 0][lm] = xv.x; xs[lk4 + 1][lm] = xv.y;
        xs[lk4 + 2][lm] = xv.z; xs[lk4 + 3][lm] = xv.w;
        ws[lk4 + 0][lm] = wv.x; ws[lk4 + 1][lm] = wv.y;
        ws[lk4 + 2][lm] = wv.z; ws[lk4 + 3][lm] = wv.w;
        __syncthreads();
#pragma unroll
        for (int kk = 0; kk < 16; kk++) {
            float xa[4], wb[4];
#pragma unroll
            for (int r = 0; r < 4; r++) xa[r] = xs[kk][tr * 4 + r];
#pragma unroll
            for (int c = 0; c < 4; c++) wb[c] = ws[kk][tc * 4 + c];
#pragma unroll
            for (int r = 0; r < 4; r++)
#pragma unroll
                for (int c = 0; c < 4; c++) acc[r][c] += xa[r] * wb[c];
        }
    }
#pragma unroll
    for (int r = 0; r < 4; r++)
        *(float4*)(g_h + (size_t)(m0 + tr * 4 + r) * F_OUT + n0 + tc * 4) =
            make_float4(acc[r][0], acc[r][1], acc[r][2], acc[r][3]);
}

// ============ K2: per-node logits + exp factor tables ============
__global__ void __launch_bounds__(256) k2_logits(const float* __restrict__ a_src,
                                                 const float* __restrict__ a_dst) {
    const int idx = blockIdx.x * 256 + threadIdx.x;
    const int n  = idx >> 2;
    const int hh = idx & 3;
    const float* hp = g_h + (size_t)n * C_OUT + hh * D_HEAD;
    const float* as = a_src + hh * D_HEAD;
    const float* ad = a_dst + hh * D_HEAD;
    float s = 0.f, t = 0.f;
#pragma unroll
    for (int d = 0; d < D_HEAD; d += 4) {
        float4 hv = *(const float4*)(hp + d);
        float4 av = *(const float4*)(as + d);
        float4 dv = *(const float4*)(ad + d);
        s += hv.x * av.x + hv.y * av.y + hv.z * av.z + hv.w * av.w;
        t += hv.x * dv.x + hv.y * dv.y + hv.z * dv.z + hv.w * dv.w;
    }
    g_S [idx] = s;
    g_F1[idx] = expf(s);
    g_F2[idx] = expf(0.2f * s);
    g_Tt  [hh * N_NODES + n] = t;
    g_E12t[hh * N_NODES + n] = make_float2(expf(t), expf(0.2f * t));
}

// ============ K2b: pack h -> fragment-order bf16 hi/lo B tiles ============
__global__ void __launch_bounds__(256) k2b_pack() {
    __shared__ float ts[32][33];
    const int tid = threadIdx.x;
    const int tx = tid & 31, ty = tid >> 5;
    const int n0 = blockIdx.x * 32;   // j dimension (nodes)
    const int c0 = blockIdx.y * 32;   // feature dimension
#pragma unroll
    for (int k = 0; k < 4; k++)
        ts[ty + 8 * k][tx] = g_h[(size_t)(n0 + ty + 8 * k) * C_OUT + c0 + tx];
    __syncthreads();

    const int lane = tid & 31;
    const int m    = lane & 3;
    const int cr   = lane >> 2;
    const int c8l  = (tid >> 5) & 3;
    const int j16l = tid >> 7;
    const int jl   = j16l * 16 + 2 * m;
    const int cl   = c8l * 8 + cr;

    const float w0 = ts[jl][cl],     w1 = ts[jl + 1][cl];
    const float w8 = ts[jl + 8][cl], w9 = ts[jl + 9][cl];
    const uint32_t u0 = __float_as_uint(w0), u1 = __float_as_uint(w1);
    const uint32_t u8 = __float_as_uint(w8), u9 = __float_as_uint(w9);
    const uint32_t xhi = (u0 >> 16) | (u1 & 0xffff0000u);
    const uint32_t yhi = (u8 >> 16) | (u9 & 0xffff0000u);
    const float l0 = w0 - __uint_as_float(u0 & 0xffff0000u);
    const float l1 = w1 - __uint_as_float(u1 & 0xffff0000u);
    const float l8 = w8 - __uint_as_float(u8 & 0xffff0000u);
    const float l9 = w9 - __uint_as_float(u9 & 0xffff0000u);
    __nv_bfloat162 p01 = __floats2bfloat162_rn(l0, l1);
    __nv_bfloat162 p89 = __floats2bfloat162_rn(l8, l9);

    const int cg  = c0 + cl;
    const int h   = cg >> 6;
    const int c8  = (cg & 63) >> 3;
    const int j16 = (n0 >> 4) + j16l;
    g_Bpk[((h * (N_NODES / 16) + j16) * 8 + c8) * 32 + lane] =
        make_uint4(xhi, yhi, *reinterpret_cast<uint32_t*>(&p01),
                   *reinterpret_cast<uint32_t*>(&p89));
}

// ---- weight for one (i, j): factored-exp masked softmax term ----
__device__ __forceinline__ float gat_w(float S, float F1, float F2,
                                       float T, float E1, float E2,
                                       float a, float& Z) {
    const float t = S + T;
    const float p = (t >= 0.f) ? F1 * E1 : F2 * E2;
    float w = 0.f;
    if (a > 0.f) { Z += p; w = a * p; }
    return w;
}

#define ADJ_STRIDE 24   // floats per smem row (16 data + 8 pad; 16B-aligned rows)

// ======= K3: fused masked-softmax + aggregation via mma.sync (HMMA) =======
// CTA: 128 thr / 4 warps = 64 rows x 128 cols (2 heads).
// adj tiles double-buffered in smem via cp.async (depth-2 pipeline); weights
// computed directly in fragment layout from smem (no shuffles).
__global__ void __launch_bounds__(128, 3) k3_agg(const float* __restrict__ adj) {
    __shared__ float adj_s[2][64][ADJ_STRIDE];

    const int tid  = threadIdx.x;
    const int wid  = tid >> 5;
    const int lane = tid & 31;
    const int i0   = blockIdx.x * 64;
    const int hp   = blockIdx.y;
    const int js   = blockIdx.z;
    const int rg   = wid >> 1;                 // row group 0..1
    const int h    = hp * 2 + (wid & 1);       // head for this warp
    const int m    = lane & 3;
    const int k0l  = 2 * m;                    // fragment k base (0,2,4,6)
    const int rloc = rg * 32 + (lane >> 2);    // local row 0..63 (fragment row)
    const int rbase = i0 + rloc;
    const int jbeg  = js * JRANGE;

    // cp.async staging role: row = tid>>1, 32B half = tid&1
    const int srow = tid >> 1;
    const int scol = (tid & 1) * 8;
    const float* sgp = adj + (size_t)(i0 + srow) * N_NODES + jbeg + scol;

    float S[4], F1[4], F2[4], Z[4];
#pragma unroll
    for (int r4 = 0; r4 < 4; r4++) {
        const int idx = (rbase + r4 * 8) * H_HEADS + h;
        S[r4] = g_S[idx]; F1[r4] = g_F1[idx]; F2[r4] = g_F2[idx];
        Z[r4] = 0.f;
    }
    const float*  Tp  = g_Tt + h * N_NODES + jbeg + k0l;
    const float4* Ep4 = (const float4*)(g_E12t + h * N_NODES + jbeg) + m;
    const uint4*  Bbase = g_Bpk + (size_t)(h * (N_NODES / 16) + (jbeg >> 4)) * 8 * 32 + lane;

    float acc[2][8][4];
#pragma unroll
    for (int mt = 0; mt < 2; mt++)
#pragma unroll
        for (int nt = 0; nt < 8; nt++)
#pragma unroll
            for (int q = 0; q < 4; q++) acc[mt][nt][q] = 0.f;

    // prologue: stage tile 0 into buf 0
    {
        const uint32_t sa = (uint32_t)__cvta_generic_to_shared(&adj_s[0][srow][scol]);
        asm volatile("cp.async.ca.shared.global [%0], [%1], 16;" :: "r"(sa), "l"(sgp) : "memory");
        asm volatile("cp.async.ca.shared.global [%0], [%1], 16;" :: "r"(sa + 16), "l"(sgp + 4) : "memory");
        asm volatile("cp.async.commit_group;" ::: "memory");
    }

#pragma unroll 1
    for (int t = 0; t < NTILES; t++) {
        const int buf = t & 1;
        const int jb  = t * 16;

        // prefetch tile t+1 into the other buffer (safe: barrier at end of
        // the weight section of iteration t-1 covers the last reads of it)
        if (t + 1 < NTILES) {
            const uint32_t sa = (uint32_t)__cvta_generic_to_shared(&adj_s[buf ^ 1][srow][scol]);
            const float* gp = sgp + jb + 16;
            asm volatile("cp.async.ca.shared.global [%0], [%1], 16;" :: "r"(sa), "l"(gp) : "memory");
            asm volatile("cp.async.ca.shared.global [%0], [%1], 16;" :: "r"(sa + 16), "l"(gp + 4) : "memory");
            asm volatile("cp.async.commit_group;" ::: "memory");
            asm volatile("cp.async.wait_group 1;" ::: "memory");
        } else {
            asm volatile("cp.async.wait_group 0;" ::: "memory");
        }
        __syncthreads();   // tile t visible to all threads

        // per-j tables for this lane's fragment k's (L1-broadcast LDGs)
        const float2 Tlo = *(const float2*)(Tp + jb);        // T[k0], T[k0+1]
        const float2 Thi = *(const float2*)(Tp + jb + 8);    // T[k0+8], T[k0+9]
        const float4 Ea  = Ep4[jb >> 1];                     // E12[k0], E12[k0+1]
        const float4 Eb  = Ep4[(jb >> 1) + 4];               // E12[k0+8], E12[k0+9]

        // weights directly in fragment layout from smem
        uint32_t ahi[2][4], alo[2][4];
#pragma unroll
        for (int r4 = 0; r4 < 4; r4++) {
            const float* arow = &adj_s[buf][rloc + r4 * 8][k0l];
            const float2 a01 = *(const float2*)(arow);
            const float2 a89 = *(const float2*)(arow + 8);
            const float w0 = gat_w(S[r4], F1[r4], F2[r4], Tlo.x, Ea.x, Ea.y, a01.x, Z[r4]);
            const float w1 = gat_w(S[r4], F1[r4], F2[r4], Tlo.y, Ea.z, Ea.w, a01.y, Z[r4]);
            const float w2 = gat_w(S[r4], F1[r4], F2[r4], Thi.x, Eb.x, Eb.y, a89.x, Z[r4]);
            const float w3 = gat_w(S[r4], F1[r4], F2[r4], Thi.y, Eb.z, Eb.w, a89.y, Z[r4]);
            const uint32_t u0 = __float_as_uint(w0), u1 = __float_as_uint(w1);
            const uint32_t u2 = __float_as_uint(w2), u3 = __float_as_uint(w3);
            const int mt = r4 >> 1, hf = r4 & 1;
            ahi[mt][hf]     = (u0 >> 16) | (u1 & 0xffff0000u);
            ahi[mt][2 + hf] = (u2 >> 16) | (u3 & 0xffff0000u);
            const float l0 = w0 - __uint_as_float(u0 & 0xffff0000u);
            const float l1 = w1 - __uint_as_float(u1 & 0xffff0000u);
            const float l2 = w2 - __uint_as_float(u2 & 0xffff0000u);
            const float l3 = w3 - __uint_as_float(u3 & 0xffff0000u);
            __nv_bfloat162 pA = __floats2bfloat162_rn(l0, l1);
            __nv_bfloat162 pB = __floats2bfloat162_rn(l2, l3);
            alo[mt][hf]     = *reinterpret_cast<const uint32_t*>(&pA);
            alo[mt][2 + hf] = *reinterpret_cast<const uint32_t*>(&pB);
        }
        __syncthreads();   // all adj_s[buf] reads done -> buffer reusable

        // B fragments (one coalesced LDG.128 per nt) + 3-product split MMAs
        const uint4* Bp = Bbase + (size_t)t * 8 * 32;
#pragma unroll
        for (int nt = 0; nt < 8; nt++) {
            const uint4 bv = Bp[nt * 32];
#pragma unroll
            for (int mt = 0; mt < 2; mt++) {
                mma16816(acc[mt][nt], ahi[mt], bv.x, bv.y);
                mma16816(acc[mt][nt], ahi[mt], bv.z, bv.w);
                mma16816(acc[mt][nt], alo[mt], bv.x, bv.y);
            }
        }
    }

    // Z: reduce over the 4 lanes of each quad (disjoint j coverage)
#pragma unroll
    for (int r4 = 0; r4 < 4; r4++) {
        Z[r4] += __shfl_xor_sync(0xffffffffu, Z[r4], 1);
        Z[r4] += __shfl_xor_sync(0xffffffffu, Z[r4], 2);
    }
    if (m == 0) {
#pragma unroll
        for (int r4 = 0; r4 < 4; r4++)
            g_Z[js][(rbase + r4 * 8) * H_HEADS + h] = Z[r4];
    }

    // U partial store
#pragma unroll
    for (int mt = 0; mt < 2; mt++) {
        const int row_lo = i0 + rg * 32 + mt * 16 + (lane >> 2);
        const int row_hi = row_lo + 8;
#pragma unroll
        for (int nt = 0; nt < 8; nt++) {
            const int col = h * 64 + nt * 8 + 2 * m;
            *(float2*)(g_U[js] + (size_t)row_lo * C_OUT + col) =
                make_float2(acc[mt][nt][0], acc[mt][nt][1]);
            *(float2*)(g_U[js] + (size_t)row_hi * C_OUT + col) =
                make_float2(acc[mt][nt][2], acc[mt][nt][3]);
        }
    }
}

// ============ K4: reduce splits + normalize (+ nan_to_num) ============
__global__ void __launch_bounds__(256) k4_final(float* __restrict__ out) {
    const int idx = blockIdx.x * 256 + threadIdx.x;   // one float4 each
    const int n  = idx >> 6;
    const int c4 = (idx & 63) * 4;
    const int hh = c4 >> 6;
    float Z = 0.f;
#pragma unroll
    for (int s = 0; s < JSPLIT; s++) Z += g_Z[s][n * H_HEADS + hh];
    float4 u = make_float4(0.f, 0.f, 0.f, 0.f);
#pragma unroll
    for (int s = 0; s < JSPLIT; s++) {
        float4 v = *(const float4*)(g_U[s] + (size_t)n * C_OUT + c4);
        u.x += v.x; u.y += v.y; u.z += v.z; u.w += v.w;
    }
    const float r = (Z > 0.f) ? (1.f / Z) : 0.f;
    *(float4*)(out + (size_t)n * C_OUT + c4) =
        make_float4(u.x * r, u.y * r, u.z * r, u.w * r);
}

// ---------------- launch ----------------
extern "C" void kernel_launch(void* const* d_in, const int* in_sizes, int n_in,
                              void* d_out, int out_size) {
    const float* x     = (const float*)d_in[0];
    const float* adj   = (const float*)d_in[1];
    const float* W     = (const float*)d_in[2];
    const float* a_src = (const float*)d_in[3];
    const float* a_dst = (const float*)d_in[4];
    float* out = (float*)d_out;

    k1_gemm<<<dim3(N_NODES / 64, F_OUT / 64), 256>>>(x, W);
    k2_logits<<<(N_NODES * H_HEADS) / 256, 256>>>(a_src, a_dst);
    k2b_pack<<<dim3(N_NODES / 32, C_OUT / 32), 256>>>();
    k3_agg<<<dim3(N_NODES / 64, 2, JSPLIT), 128>>>(adj);
    k4_final<<<(N_NODES * C_OUT / 4) / 256, 256>>>(out);
}

// round 12
// speedup vs baseline: 1.1800x; 1.1541x over previous
#include <cuda_runtime.h>
#include <cuda_bf16.h>
#include <cstdint>

// Problem constants
#define N_NODES 4096
#define F_IN    256
#define F_OUT   256
#define H_HEADS 4
#define D_HEAD  64
#define C_OUT   256

#define JSPLIT  4
#define JRANGE  (N_NODES / JSPLIT)   // 1024 per CTA
#define NTILES  (JRANGE / 16)        // 64
#define NN16    (N_NODES / 16)       // 256

// ---------------- scratch (no cudaMalloc allowed) ----------------
__device__ __align__(16) float g_h  [N_NODES * F_OUT];
__device__ __align__(16) float g_S  [N_NODES * H_HEADS];      // [n*4+h]
__device__ __align__(16) float g_F1 [N_NODES * H_HEADS];
__device__ __align__(16) float g_F2 [N_NODES * H_HEADS];
__device__ __align__(16) float g_Tt [H_HEADS * N_NODES];      // [h][n]
__device__ __align__(16) float2 g_E12t[H_HEADS * N_NODES];    // [h][n] = {E1, E2}
// fragment-packed B: [h][j16][c8][lane] -> uint4{hi_b0, hi_b1, lo_b0, lo_b1}
__device__ uint4 g_Bpk[H_HEADS * NN16 * 8 * 32];
__device__ __align__(16) float g_U [JSPLIT][N_NODES * C_OUT];
__device__ __align__(16) float g_Z [JSPLIT][N_NODES * H_HEADS];

// ---------------- mma.sync helper (sm_80+ portable HMMA) ----------------
__device__ __forceinline__ void mma16816(float* c, const uint32_t* a,
                                         uint32_t b0, uint32_t b1) {
    asm volatile(
        "mma.sync.aligned.m16n8k16.row.col.f32.bf16.bf16.f32 "
        "{%0,%1,%2,%3}, {%4,%5,%6,%7}, {%8,%9}, {%0,%1,%2,%3};"
        : "+f"(c[0]), "+f"(c[1]), "+f"(c[2]), "+f"(c[3])
        : "r"(a[0]), "r"(a[1]), "r"(a[2]), "r"(a[3]), "r"(b0), "r"(b1));
}

__device__ __forceinline__ void cp16(uint32_t dst, const void* src) {
    asm volatile("cp.async.cg.shared.global [%0], [%1], 16;"
                 :: "r"(dst), "l"(src) : "memory");
}

// ================= K1: h = x @ W^T  (4096x256x256) =================
__global__ void __launch_bounds__(256) k1_gemm(const float* __restrict__ x,
                                               const float* __restrict__ W) {
    __shared__ float xs[16][68];
    __shared__ float ws[16][68];
    const int tid = threadIdx.x;
    const int m0 = blockIdx.x * 64;
    const int n0 = blockIdx.y * 64;
    const int tr = tid >> 4, tc = tid & 15;
    const int lm = tid >> 2, lk4 = (tid & 3) << 2;

    float acc[4][4];
#pragma unroll
    for (int r = 0; r < 4; r++)
#pragma unroll
        for (int c = 0; c < 4; c++) acc[r][c] = 0.f;

    for (int k0 = 0; k0 < F_IN; k0 += 16) {
        float4 xv = *(const float4*)(x + (size_t)(m0 + lm) * F_IN + k0 + lk4);
        float4 wv = *(const float4*)(W + (size_t)(n0 + lm) * F_IN + k0 + lk4);
        __syncthreads();
        xs[lk4 + 0][lm] = xv.x; xs[lk4 + 1][lm] = xv.y;
        xs[lk4 + 2][lm] = xv.z; xs[lk4 + 3][lm] = xv.w;
        ws[lk4 + 0][lm] = wv.x; ws[lk4 + 1][lm] = wv.y;
        ws[lk4 + 2][lm] = wv.z; ws[lk4 + 3][lm] = wv.w;
        __syncthreads();
#pragma unroll
        for (int kk = 0; kk < 16; kk++) {
            float xa[4], wb[4];
#pragma unroll
            for (int r = 0; r < 4; r++) xa[r] = xs[kk][tr * 4 + r];
#pragma unroll
            for (int c = 0; c < 4; c++) wb[c] = ws[kk][tc * 4 + c];
#pragma unroll
            for (int r = 0; r < 4; r++)
#pragma unroll
                for (int c = 0; c < 4; c++) acc[r][c] += xa[r] * wb[c];
        }
    }
#pragma unroll
    for (int r = 0; r < 4; r++)
        *(float4*)(g_h + (size_t)(m0 + tr * 4 + r) * F_OUT + n0 + tc * 4) =
            make_float4(acc[r][0], acc[r][1], acc[r][2], acc[r][3]);
}

// ============ K2: per-node logits + exp factor tables ============
__global__ void __launch_bounds__(256) k2_logits(const float* __restrict__ a_src,
                                                 const float* __restrict__ a_dst) {
    const int idx = blockIdx.x * 256 + threadIdx.x;
    const int n  = idx >> 2;
    const int hh = idx & 3;
    const float* hp = g_h + (size_t)n * C_OUT + hh * D_HEAD;
    const float* as = a_src + hh * D_HEAD;
    const float* ad = a_dst + hh * D_HEAD;
    float s = 0.f, t = 0.f;
#pragma unroll
    for (int d = 0; d < D_HEAD; d += 4) {
        float4 hv = *(const float4*)(hp + d);
        float4 av = *(const float4*)(as + d);
        float4 dv = *(const float4*)(ad + d);
        s += hv.x * av.x + hv.y * av.y + hv.z * av.z + hv.w * av.w;
        t += hv.x * dv.x + hv.y * dv.y + hv.z * dv.z + hv.w * dv.w;
    }
    g_S [idx] = s;
    g_F1[idx] = expf(s);
    g_F2[idx] = expf(0.2f * s);
    g_Tt  [hh * N_NODES + n] = t;
    g_E12t[hh * N_NODES + n] = make_float2(expf(t), expf(0.2f * t));
}

// ============ K2b: pack h -> fragment-order bf16 hi/lo B tiles ============
__global__ void __launch_bounds__(256) k2b_pack() {
    __shared__ float ts[32][33];
    const int tid = threadIdx.x;
    const int tx = tid & 31, ty = tid >> 5;
    const int n0 = blockIdx.x * 32;   // j dimension (nodes)
    const int c0 = blockIdx.y * 32;   // feature dimension
#pragma unroll
    for (int k = 0; k < 4; k++)
        ts[ty + 8 * k][tx] = g_h[(size_t)(n0 + ty + 8 * k) * C_OUT + c0 + tx];
    __syncthreads();

    const int lane = tid & 31;
    const int m    = lane & 3;
    const int cr   = lane >> 2;
    const int c8l  = (tid >> 5) & 3;
    const int j16l = tid >> 7;
    const int jl   = j16l * 16 + 2 * m;
    const int cl   = c8l * 8 + cr;

    const float w0 = ts[jl][cl],     w1 = ts[jl + 1][cl];
    const float w8 = ts[jl + 8][cl], w9 = ts[jl + 9][cl];
    const uint32_t u0 = __float_as_uint(w0), u1 = __float_as_uint(w1);
    const uint32_t u8 = __float_as_uint(w8), u9 = __float_as_uint(w9);
    const uint32_t xhi = (u0 >> 16) | (u1 & 0xffff0000u);
    const uint32_t yhi = (u8 >> 16) | (u9 & 0xffff0000u);
    const float l0 = w0 - __uint_as_float(u0 & 0xffff0000u);
    const float l1 = w1 - __uint_as_float(u1 & 0xffff0000u);
    const float l8 = w8 - __uint_as_float(u8 & 0xffff0000u);
    const float l9 = w9 - __uint_as_float(u9 & 0xffff0000u);
    __nv_bfloat162 p01 = __floats2bfloat162_rn(l0, l1);
    __nv_bfloat162 p89 = __floats2bfloat162_rn(l8, l9);

    const int cg  = c0 + cl;
    const int h   = cg >> 6;
    const int c8  = (cg & 63) >> 3;
    const int j16 = (n0 >> 4) + j16l;
    g_Bpk[((h * NN16 + j16) * 8 + c8) * 32 + lane] =
        make_uint4(xhi, yhi, *reinterpret_cast<uint32_t*>(&p01),
                   *reinterpret_cast<uint32_t*>(&p89));
}

// ---- weight for one (i, j): factored-exp masked softmax term ----
__device__ __forceinline__ float gat_w(float S, float F1, float F2,
                                       float T, float E1, float E2,
                                       float a, float& Z) {
    const float t = S + T;
    const float p = (t >= 0.f) ? F1 * E1 : F2 * E2;
    float w = 0.f;
    if (a > 0.f) { Z += p; w = a * p; }
    return w;
}

#define ADJ_STRIDE 24   // floats per smem row (16 data + 8 pad)

// ======= K3: fused masked-softmax + aggregation via mma.sync (HMMA) =======
// CTA: 128 thr / 4 warps = 64 rows x 128 cols (2 heads).
// adj AND B tiles double-buffered in smem via cp.async; one barrier per tile;
// mainloop has no LDG in the MMA dependency chain.
__global__ void __launch_bounds__(128, 3) k3_agg(const float* __restrict__ adj) {
    __shared__ float adj_s[2][64][ADJ_STRIDE];
    __shared__ uint4 b_s[2][2][8][32];   // [buf][head-in-pair][c8][lane]

    const int tid  = threadIdx.x;
    const int wid  = tid >> 5;
    const int lane = tid & 31;
    const int i0   = blockIdx.x * 64;
    const int hp   = blockIdx.y;
    const int js   = blockIdx.z;
    const int rg   = wid >> 1;                 // row group 0..1
    const int hw   = wid & 1;                  // head-in-pair for this warp
    const int h    = hp * 2 + hw;
    const int m    = lane & 3;
    const int k0l  = 2 * m;                    // fragment k base (0,2,4,6)
    const int rloc = rg * 32 + (lane >> 2);    // local row 0..63 (fragment row)
    const int rbase = i0 + rloc;
    const int jbeg  = js * JRANGE;

    // ---- staging roles ----
    // adj: 64 rows x 64B; thread -> (row = tid>>1, 32B half = tid&1)
    const int srow = tid >> 1;
    const int scol = (tid & 1) * 8;
    const float* sgp = adj + (size_t)(i0 + srow) * N_NODES + jbeg + scol;
    const uint32_t adj_dst0 = (uint32_t)__cvta_generic_to_shared(&adj_s[0][srow][scol]);
    const uint32_t adj_buf_sz = (uint32_t)(64 * ADJ_STRIDE * 4);
    // B: 512 chunks of 16B per tile; thread stages 4 (idx = tid + k*128)
    const uint4* bsrc[4];
#pragma unroll
    for (int k = 0; k < 4; k++) {
        const int idx = tid + k * 128;
        bsrc[k] = g_Bpk + ((size_t)(hp * 2 + (idx >> 8)) * NN16 + (jbeg >> 4)) * 256
                        + (idx & 255);
    }
    const uint32_t b_dst0 = (uint32_t)__cvta_generic_to_shared(&b_s[0][0][0][0]) + tid * 16;

    float S[4], F1[4], F2[4], Z[4];
#pragma unroll
    for (int r4 = 0; r4 < 4; r4++) {
        const int idx = (rbase + r4 * 8) * H_HEADS + h;
        S[r4] = g_S[idx]; F1[r4] = g_F1[idx]; F2[r4] = g_F2[idx];
        Z[r4] = 0.f;
    }
    const float*  Tp  = g_Tt + h * N_NODES + jbeg + k0l;
    const float4* Ep4 = (const float4*)(g_E12t + h * N_NODES + jbeg) + m;

    float acc[2][8][4];
#pragma unroll
    for (int mt = 0; mt < 2; mt++)
#pragma unroll
        for (int nt = 0; nt < 8; nt++)
#pragma unroll
            for (int q = 0; q < 4; q++) acc[mt][nt][q] = 0.f;

    // prologue: stage tile 0 into buf 0
    {
        cp16(adj_dst0, sgp);
        cp16(adj_dst0 + 16, sgp + 4);
#pragma unroll
        for (int k = 0; k < 4; k++) cp16(b_dst0 + k * 2048, bsrc[k]);
        asm volatile("cp.async.commit_group;" ::: "memory");
    }

#pragma unroll 1
    for (int t = 0; t < NTILES; t++) {
        const int buf = t & 1;
        const int jb  = t * 16;

        asm volatile("cp.async.wait_group 0;" ::: "memory");
        __syncthreads();   // tile t visible; all warps done reading buf^1

        // prefetch tile t+1 into buf^1 (overlaps with compute below)
        if (t + 1 < NTILES) {
            const uint32_t ad = adj_dst0 + (buf ^ 1) * adj_buf_sz;
            const float* gp = sgp + jb + 16;
            cp16(ad, gp);
            cp16(ad + 16, gp + 4);
            const uint32_t bd = b_dst0 + (buf ^ 1) * 8192;
#pragma unroll
            for (int k = 0; k < 4; k++)
                cp16(bd + k * 2048, bsrc[k] + (size_t)(t + 1) * 256);
            asm volatile("cp.async.commit_group;" ::: "memory");
        }

        // per-j tables for this lane's fragment k's (L1-hot LDGs)
        const float2 Tlo = *(const float2*)(Tp + jb);
        const float2 Thi = *(const float2*)(Tp + jb + 8);
        const float4 Ea  = Ep4[jb >> 1];
        const float4 Eb  = Ep4[(jb >> 1) + 4];

        // weights directly in fragment layout from smem
        uint32_t ahi[2][4], alo[2][4];
#pragma unroll
        for (int r4 = 0; r4 < 4; r4++) {
            const float* arow = &adj_s[buf][rloc + r4 * 8][k0l];
            const float2 a01 = *(const float2*)(arow);
            const float2 a89 = *(const float2*)(arow + 8);
            const float w0 = gat_w(S[r4], F1[r4], F2[r4], Tlo.x, Ea.x, Ea.y, a01.x, Z[r4]);
            const float w1 = gat_w(S[r4], F1[r4], F2[r4], Tlo.y, Ea.z, Ea.w, a01.y, Z[r4]);
            const float w2 = gat_w(S[r4], F1[r4], F2[r4], Thi.x, Eb.x, Eb.y, a89.x, Z[r4]);
            const float w3 = gat_w(S[r4], F1[r4], F2[r4], Thi.y, Eb.z, Eb.w, a89.y, Z[r4]);
            const uint32_t u0 = __float_as_uint(w0), u1 = __float_as_uint(w1);
            const uint32_t u2 = __float_as_uint(w2), u3 = __float_as_uint(w3);
            const int mt = r4 >> 1, hf = r4 & 1;
            ahi[mt][hf]     = (u0 >> 16) | (u1 & 0xffff0000u);
            ahi[mt][2 + hf] = (u2 >> 16) | (u3 & 0xffff0000u);
            const float l0 = w0 - __uint_as_float(u0 & 0xffff0000u);
            const float l1 = w1 - __uint_as_float(u1 & 0xffff0000u);
            const float l2 = w2 - __uint_as_float(u2 & 0xffff0000u);
            const float l3 = w3 - __uint_as_float(u3 & 0xffff0000u);
            __nv_bfloat162 pA = __floats2bfloat162_rn(l0, l1);
            __nv_bfloat162 pB = __floats2bfloat162_rn(l2, l3);
            alo[mt][hf]     = *reinterpret_cast<const uint32_t*>(&pA);
            alo[mt][2 + hf] = *reinterpret_cast<const uint32_t*>(&pB);
        }

        // B fragments from smem (LDS.128) + 3-product split MMAs
#pragma unroll
        for (int nt = 0; nt < 8; nt++) {
            const uint4 bv = b_s[buf][hw][nt][lane];
#pragma unroll
            for (int mt = 0; mt < 2; mt++) {
                mma16816(acc[mt][nt], ahi[mt], bv.x, bv.y);
                mma16816(acc[mt][nt], ahi[mt], bv.z, bv.w);
                mma16816(acc[mt][nt], alo[mt], bv.x, bv.y);
            }
        }
    }

    // Z: reduce over the 4 lanes of each quad (disjoint j coverage)
#pragma unroll
    for (int r4 = 0; r4 < 4; r4++) {
        Z[r4] += __shfl_xor_sync(0xffffffffu, Z[r4], 1);
        Z[r4] += __shfl_xor_sync(0xffffffffu, Z[r4], 2);
    }
    if (m == 0) {
#pragma unroll
        for (int r4 = 0; r4 < 4; r4++)
            g_Z[js][(rbase + r4 * 8) * H_HEADS + h] = Z[r4];
    }

    // U partial store
#pragma unroll
    for (int mt = 0; mt < 2; mt++) {
        const int row_lo = i0 + rg * 32 + mt * 16 + (lane >> 2);
        const int row_hi = row_lo + 8;
#pragma unroll
        for (int nt = 0; nt < 8; nt++) {
            const int col = h * 64 + nt * 8 + 2 * m;
            *(float2*)(g_U[js] + (size_t)row_lo * C_OUT + col) =
                make_float2(acc[mt][nt][0], acc[mt][nt][1]);
            *(float2*)(g_U[js] + (size_t)row_hi * C_OUT + col) =
                make_float2(acc[mt][nt][2], acc[mt][nt][3]);
        }
    }
}

// ============ K4: reduce splits + normalize (+ nan_to_num) ============
__global__ void __launch_bounds__(256) k4_final(float* __restrict__ out) {
    const int idx = blockIdx.x * 256 + threadIdx.x;   // one float4 each
    const int n  = idx >> 6;
    const int c4 = (idx & 63) * 4;
    const int hh = c4 >> 6;
    float Z = 0.f;
#pragma unroll
    for (int s = 0; s < JSPLIT; s++) Z += g_Z[s][n * H_HEADS + hh];
    float4 u = make_float4(0.f, 0.f, 0.f, 0.f);
#pragma unroll
    for (int s = 0; s < JSPLIT; s++) {
        float4 v = *(const float4*)(g_U[s] + (size_t)n * C_OUT + c4);
        u.x += v.x; u.y += v.y; u.z += v.z; u.w += v.w;
    }
    const float r = (Z > 0.f) ? (1.f / Z) : 0.f;
    *(float4*)(out + (size_t)n * C_OUT + c4) =
        make_float4(u.x * r, u.y * r, u.z * r, u.w * r);
}

// ---------------- launch ----------------
extern "C" void kernel_launch(void* const* d_in, const int* in_sizes, int n_in,
                              void* d_out, int out_size) {
    const float* x     = (const float*)d_in[0];
    const float* adj   = (const float*)d_in[1];
    const float* W     = (const float*)d_in[2];
    const float* a_src = (const float*)d_in[3];
    const float* a_dst = (const float*)d_in[4];
    float* out = (float*)d_out;

    k1_gemm<<<dim3(N_NODES / 64, F_OUT / 64), 256>>>(x, W);
    k2_logits<<<(N_NODES * H_HEADS) / 256, 256>>>(a_src, a_dst);
    k2b_pack<<<dim3(N_NODES / 32, C_OUT / 32), 256>>>();
    k3_agg<<<dim3(N_NODES / 64, 2, JSPLIT), 128>>>(adj);
    k4_final<<<(N_NODES * C_OUT / 4) / 256, 256>>>(out);
}

// round 13
// speedup vs baseline: 1.3248x; 1.1227x over previous
#include <cuda_runtime.h>
#include <cuda_bf16.h>
#include <cstdint>

// Problem constants
#define N_NODES 4096
#define F_IN    256
#define F_OUT   256
#define H_HEADS 4
#define D_HEAD  64
#define C_OUT   256

#define JSPLIT  8
#define JRANGE  (N_NODES / JSPLIT)   // 512 per CTA
#define NTILES  (JRANGE / 16)        // 32
#define NN16    (N_NODES / 16)       // 256

// ---------------- scratch (no cudaMalloc allowed) ----------------
__device__ __align__(16) float g_h  [N_NODES * F_OUT];
__device__ __align__(16) float g_S  [N_NODES * H_HEADS];      // [n*4+h]
__device__ __align__(16) float g_F1 [N_NODES * H_HEADS];
__device__ __align__(16) float g_F2 [N_NODES * H_HEADS];
__device__ __align__(16) float g_Tt [H_HEADS * N_NODES];      // [h][n]
__device__ __align__(16) float2 g_E12t[H_HEADS * N_NODES];    // [h][n] = {E1, E2}
// fragment-packed B: [h][j16][c8][lane] -> uint4{hi_b0, hi_b1, lo_b0, lo_b1}
__device__ uint4 g_Bpk[H_HEADS * NN16 * 8 * 32];
__device__ __align__(16) float g_U [JSPLIT][N_NODES * C_OUT];
__device__ __align__(16) float g_Z [JSPLIT][N_NODES * H_HEADS];

// ---------------- mma.sync helper (sm_80+ portable HMMA) ----------------
__device__ __forceinline__ void mma16816(float* c, const uint32_t* a,
                                         uint32_t b0, uint32_t b1) {
    asm volatile(
        "mma.sync.aligned.m16n8k16.row.col.f32.bf16.bf16.f32 "
        "{%0,%1,%2,%3}, {%4,%5,%6,%7}, {%8,%9}, {%0,%1,%2,%3};"
        : "+f"(c[0]), "+f"(c[1]), "+f"(c[2]), "+f"(c[3])
        : "r"(a[0]), "r"(a[1]), "r"(a[2]), "r"(a[3]), "r"(b0), "r"(b1));
}

__device__ __forceinline__ void cp16(uint32_t dst, const void* src) {
    asm volatile("cp.async.cg.shared.global [%0], [%1], 16;"
                 :: "r"(dst), "l"(src) : "memory");
}

// ================= K1: h = x @ W^T  (4096x256x256) =================
__global__ void __launch_bounds__(256) k1_gemm(const float* __restrict__ x,
                                               const float* __restrict__ W) {
    __shared__ float xs[16][68];
    __shared__ float ws[16][68];
    const int tid = threadIdx.x;
    const int m0 = blockIdx.x * 64;
    const int n0 = blockIdx.y * 64;
    const int tr = tid >> 4, tc = tid & 15;
    const int lm = tid >> 2, lk4 = (tid & 3) << 2;

    float acc[4][4];
#pragma unroll
    for (int r = 0; r < 4; r++)
#pragma unroll
        for (int c = 0; c < 4; c++) acc[r][c] = 0.f;

    for (int k0 = 0; k0 < F_IN; k0 += 16) {
        float4 xv = *(const float4*)(x + (size_t)(m0 + lm) * F_IN + k0 + lk4);
        float4 wv = *(const float4*)(W + (size_t)(n0 + lm) * F_IN + k0 + lk4);
        __syncthreads();
        xs[lk4 + 0][lm] = xv.x; xs[lk4 + 1][lm] = xv.y;
        xs[lk4 + 2][lm] = xv.z; xs[lk4 + 3][lm] = xv.w;
        ws[lk4 + 0][lm] = wv.x; ws[lk4 + 1][lm] = wv.y;
        ws[lk4 + 2][lm] = wv.z; ws[lk4 + 3][lm] = wv.w;
        __syncthreads();
#pragma unroll
        for (int kk = 0; kk < 16; kk++) {
            float xa[4], wb[4];
#pragma unroll
            for (int r = 0; r < 4; r++) xa[r] = xs[kk][tr * 4 + r];
#pragma unroll
            for (int c = 0; c < 4; c++) wb[c] = ws[kk][tc * 4 + c];
#pragma unroll
            for (int r = 0; r < 4; r++)
#pragma unroll
                for (int c = 0; c < 4; c++) acc[r][c] += xa[r] * wb[c];
        }
    }
#pragma unroll
    for (int r = 0; r < 4; r++)
        *(float4*)(g_h + (size_t)(m0 + tr * 4 + r) * F_OUT + n0 + tc * 4) =
            make_float4(acc[r][0], acc[r][1], acc[r][2], acc[r][3]);
}

// ============ K2: per-node logits + exp factor tables ============
__global__ void __launch_bounds__(256) k2_logits(const float* __restrict__ a_src,
                                                 const float* __restrict__ a_dst) {
    const int idx = blockIdx.x * 256 + threadIdx.x;
    const int n  = idx >> 2;
    const int hh = idx & 3;
    const float* hp = g_h + (size_t)n * C_OUT + hh * D_HEAD;
    const float* as = a_src + hh * D_HEAD;
    const float* ad = a_dst + hh * D_HEAD;
    float s = 0.f, t = 0.f;
#pragma unroll
    for (int d = 0; d < D_HEAD; d += 4) {
        float4 hv = *(const float4*)(hp + d);
        float4 av = *(const float4*)(as + d);
        float4 dv = *(const float4*)(ad + d);
        s += hv.x * av.x + hv.y * av.y + hv.z * av.z + hv.w * av.w;
        t += hv.x * dv.x + hv.y * dv.y + hv.z * dv.z + hv.w * dv.w;
    }
    g_S [idx] = s;
    g_F1[idx] = expf(s);
    g_F2[idx] = expf(0.2f * s);
    g_Tt  [hh * N_NODES + n] = t;
    g_E12t[hh * N_NODES + n] = make_float2(expf(t), expf(0.2f * t));
}

// ============ K2b: pack h -> fragment-order bf16 hi/lo B tiles ============
__global__ void __launch_bounds__(256) k2b_pack() {
    __shared__ float ts[32][33];
    const int tid = threadIdx.x;
    const int tx = tid & 31, ty = tid >> 5;
    const int n0 = blockIdx.x * 32;   // j dimension (nodes)
    const int c0 = blockIdx.y * 32;   // feature dimension
#pragma unroll
    for (int k = 0; k < 4; k++)
        ts[ty + 8 * k][tx] = g_h[(size_t)(n0 + ty + 8 * k) * C_OUT + c0 + tx];
    __syncthreads();

    const int lane = tid & 31;
    const int m    = lane & 3;
    const int cr   = lane >> 2;
    const int c8l  = (tid >> 5) & 3;
    const int j16l = tid >> 7;
    const int jl   = j16l * 16 + 2 * m;
    const int cl   = c8l * 8 + cr;

    const float w0 = ts[jl][cl],     w1 = ts[jl + 1][cl];
    const float w8 = ts[jl + 8][cl], w9 = ts[jl + 9][cl];
    const uint32_t u0 = __float_as_uint(w0), u1 = __float_as_uint(w1);
    const uint32_t u8 = __float_as_uint(w8), u9 = __float_as_uint(w9);
    const uint32_t xhi = (u0 >> 16) | (u1 & 0xffff0000u);
    const uint32_t yhi = (u8 >> 16) | (u9 & 0xffff0000u);
    const float l0 = w0 - __uint_as_float(u0 & 0xffff0000u);
    const float l1 = w1 - __uint_as_float(u1 & 0xffff0000u);
    const float l8 = w8 - __uint_as_float(u8 & 0xffff0000u);
    const float l9 = w9 - __uint_as_float(u9 & 0xffff0000u);
    __nv_bfloat162 p01 = __floats2bfloat162_rn(l0, l1);
    __nv_bfloat162 p89 = __floats2bfloat162_rn(l8, l9);

    const int cg  = c0 + cl;
    const int h   = cg >> 6;
    const int c8  = (cg & 63) >> 3;
    const int j16 = (n0 >> 4) + j16l;
    g_Bpk[((h * NN16 + j16) * 8 + c8) * 32 + lane] =
        make_uint4(xhi, yhi, *reinterpret_cast<uint32_t*>(&p01),
                   *reinterpret_cast<uint32_t*>(&p89));
}

// ---- weight for one (i, j): factored-exp masked softmax term ----
// branch-free: w = max(a,0) * p  (identical values to predicated form)
__device__ __forceinline__ float gat_w(float S, float F1, float F2,
                                       float T, float E1, float E2,
                                       float a, float& Z) {
    const float t = S + T;
    const float p = (t >= 0.f) ? F1 * E1 : F2 * E2;
    Z += (a > 0.f) ? p : 0.f;
    return fmaxf(a, 0.f) * p;
}

#define ADJ_STRIDE 24   // floats per smem row (16 data + 8 pad)

// ======= K3: fused masked-softmax + aggregation via mma.sync (HMMA) =======
// CTA: 128 thr / 4 warps = 64 rows x 128 cols (2 heads).
// adj AND B tiles double-buffered in smem via cp.async; one barrier per tile.
// JSPLIT=8 -> 1024 CTAs for wave smoothing at 3 CTAs/SM residency.
__global__ void __launch_bounds__(128, 3) k3_agg(const float* __restrict__ adj) {
    __shared__ float adj_s[2][64][ADJ_STRIDE];
    __shared__ uint4 b_s[2][2][8][32];   // [buf][head-in-pair][c8][lane]

    const int tid  = threadIdx.x;
    const int wid  = tid >> 5;
    const int lane = tid & 31;
    const int i0   = blockIdx.x * 64;
    const int hp   = blockIdx.y;
    const int js   = blockIdx.z;
    const int rg   = wid >> 1;                 // row group 0..1
    const int hw   = wid & 1;                  // head-in-pair for this warp
    const int h    = hp * 2 + hw;
    const int m    = lane & 3;
    const int k0l  = 2 * m;                    // fragment k base (0,2,4,6)
    const int rloc = rg * 32 + (lane >> 2);    // local row 0..63 (fragment row)
    const int rbase = i0 + rloc;
    const int jbeg  = js * JRANGE;

    // ---- staging roles ----
    const int srow = tid >> 1;
    const int scol = (tid & 1) * 8;
    const float* sgp = adj + (size_t)(i0 + srow) * N_NODES + jbeg + scol;
    const uint32_t adj_dst0 = (uint32_t)__cvta_generic_to_shared(&adj_s[0][srow][scol]);
    const uint32_t adj_buf_sz = (uint32_t)(64 * ADJ_STRIDE * 4);
    const uint4* bsrc[4];
#pragma unroll
    for (int k = 0; k < 4; k++) {
        const int idx = tid + k * 128;
        bsrc[k] = g_Bpk + ((size_t)(hp * 2 + (idx >> 8)) * NN16 + (jbeg >> 4)) * 256
                        + (idx & 255);
    }
    const uint32_t b_dst0 = (uint32_t)__cvta_generic_to_shared(&b_s[0][0][0][0]) + tid * 16;

    float S[4], F1[4], F2[4], Z[4];
#pragma unroll
    for (int r4 = 0; r4 < 4; r4++) {
        const int idx = (rbase + r4 * 8) * H_HEADS + h;
        S[r4] = g_S[idx]; F1[r4] = g_F1[idx]; F2[r4] = g_F2[idx];
        Z[r4] = 0.f;
    }
    const float*  Tp  = g_Tt + h * N_NODES + jbeg + k0l;
    const float4* Ep4 = (const float4*)(g_E12t + h * N_NODES + jbeg) + m;

    float acc[2][8][4];
#pragma unroll
    for (int mt = 0; mt < 2; mt++)
#pragma unroll
        for (int nt = 0; nt < 8; nt++)
#pragma unroll
            for (int q = 0; q < 4; q++) acc[mt][nt][q] = 0.f;

    // prologue: stage tile 0 into buf 0
    {
        cp16(adj_dst0, sgp);
        cp16(adj_dst0 + 16, sgp + 4);
#pragma unroll
        for (int k = 0; k < 4; k++) cp16(b_dst0 + k * 2048, bsrc[k]);
        asm volatile("cp.async.commit_group;" ::: "memory");
    }

#pragma unroll 1
    for (int t = 0; t < NTILES; t++) {
        const int buf = t & 1;
        const int jb  = t * 16;

        asm volatile("cp.async.wait_group 0;" ::: "memory");
        __syncthreads();   // tile t visible; all warps done reading buf^1

        // prefetch tile t+1 into buf^1 (overlaps with compute below)
        if (t + 1 < NTILES) {
            const uint32_t ad = adj_dst0 + (buf ^ 1) * adj_buf_sz;
            const float* gp = sgp + jb + 16;
            cp16(ad, gp);
            cp16(ad + 16, gp + 4);
            const uint32_t bd = b_dst0 + (buf ^ 1) * 8192;
#pragma unroll
            for (int k = 0; k < 4; k++)
                cp16(bd + k * 2048, bsrc[k] + (size_t)(t + 1) * 256);
            asm volatile("cp.async.commit_group;" ::: "memory");
        }

        // per-j tables for this lane's fragment k's (L1-hot LDGs)
        const float2 Tlo = *(const float2*)(Tp + jb);
        const float2 Thi = *(const float2*)(Tp + jb + 8);
        const float4 Ea  = Ep4[jb >> 1];
        const float4 Eb  = Ep4[(jb >> 1) + 4];

        // weights directly in fragment layout from smem
        uint32_t ahi[2][4], alo[2][4];
#pragma unroll
        for (int r4 = 0; r4 < 4; r4++) {
            const float* arow = &adj_s[buf][rloc + r4 * 8][k0l];
            const float2 a01 = *(const float2*)(arow);
            const float2 a89 = *(const float2*)(arow + 8);
            const float w0 = gat_w(S[r4], F1[r4], F2[r4], Tlo.x, Ea.x, Ea.y, a01.x, Z[r4]);
            const float w1 = gat_w(S[r4], F1[r4], F2[r4], Tlo.y, Ea.z, Ea.w, a01.y, Z[r4]);
            const float w2 = gat_w(S[r4], F1[r4], F2[r4], Thi.x, Eb.x, Eb.y, a89.x, Z[r4]);
            const float w3 = gat_w(S[r4], F1[r4], F2[r4], Thi.y, Eb.z, Eb.w, a89.y, Z[r4]);
            const uint32_t u0 = __float_as_uint(w0), u1 = __float_as_uint(w1);
            const uint32_t u2 = __float_as_uint(w2), u3 = __float_as_uint(w3);
            const int mt = r4 >> 1, hf = r4 & 1;
            ahi[mt][hf]     = (u0 >> 16) | (u1 & 0xffff0000u);
            ahi[mt][2 + hf] = (u2 >> 16) | (u3 & 0xffff0000u);
            const float l0 = w0 - __uint_as_float(u0 & 0xffff0000u);
            const float l1 = w1 - __uint_as_float(u1 & 0xffff0000u);
            const float l2 = w2 - __uint_as_float(u2 & 0xffff0000u);
            const float l3 = w3 - __uint_as_float(u3 & 0xffff0000u);
            __nv_bfloat162 pA = __floats2bfloat162_rn(l0, l1);
            __nv_bfloat162 pB = __floats2bfloat162_rn(l2, l3);
            alo[mt][hf]     = *reinterpret_cast<const uint32_t*>(&pA);
            alo[mt][2 + hf] = *reinterpret_cast<const uint32_t*>(&pB);
        }

        // B fragments from smem (LDS.128) + 3-product split MMAs
#pragma unroll
        for (int nt = 0; nt < 8; nt++) {
            const uint4 bv = b_s[buf][hw][nt][lane];
#pragma unroll
            for (int mt = 0; mt < 2; mt++) {
                mma16816(acc[mt][nt], ahi[mt], bv.x, bv.y);
                mma16816(acc[mt][nt], ahi[mt], bv.z, bv.w);
                mma16816(acc[mt][nt], alo[mt], bv.x, bv.y);
            }
        }
    }

    // Z: reduce over the 4 lanes of each quad (disjoint j coverage)
#pragma unroll
    for (int r4 = 0; r4 < 4; r4++) {
        Z[r4] += __shfl_xor_sync(0xffffffffu, Z[r4], 1);
        Z[r4] += __shfl_xor_sync(0xffffffffu, Z[r4], 2);
    }
    if (m == 0) {
#pragma unroll
        for (int r4 = 0; r4 < 4; r4++)
            g_Z[js][(rbase + r4 * 8) * H_HEADS + h] = Z[r4];
    }

    // U partial store
#pragma unroll
    for (int mt = 0; mt < 2; mt++) {
        const int row_lo = i0 + rg * 32 + mt * 16 + (lane >> 2);
        const int row_hi = row_lo + 8;
#pragma unroll
        for (int nt = 0; nt < 8; nt++) {
            const int col = h * 64 + nt * 8 + 2 * m;
            *(float2*)(g_U[js] + (size_t)row_lo * C_OUT + col) =
                make_float2(acc[mt][nt][0], acc[mt][nt][1]);
            *(float2*)(g_U[js] + (size_t)row_hi * C_OUT + col) =
                make_float2(acc[mt][nt][2], acc[mt][nt][3]);
        }
    }
}

// ============ K4: reduce splits + normalize (+ nan_to_num) ============
__global__ void __launch_bounds__(256) k4_final(float* __restrict__ out) {
    const int idx = blockIdx.x * 256 + threadIdx.x;   // one float4 each
    const int n  = idx >> 6;
    const int c4 = (idx & 63) * 4;
    const int hh = c4 >> 6;
    float Z = 0.f;
#pragma unroll
    for (int s = 0; s < JSPLIT; s++) Z += g_Z[s][n * H_HEADS + hh];
    float4 u = make_float4(0.f, 0.f, 0.f, 0.f);
#pragma unroll
    for (int s = 0; s < JSPLIT; s++) {
        float4 v = *(const float4*)(g_U[s] + (size_t)n * C_OUT + c4);
        u.x += v.x; u.y += v.y; u.z += v.z; u.w += v.w;
    }
    const float r = (Z > 0.f) ? (1.f / Z) : 0.f;
    *(float4*)(out + (size_t)n * C_OUT + c4) =
        make_float4(u.x * r, u.y * r, u.z * r, u.w * r);
}

// ---------------- launch ----------------
extern "C" void kernel_launch(void* const* d_in, const int* in_sizes, int n_in,
                              void* d_out, int out_size) {
    const float* x     = (const float*)d_in[0];
    const float* adj   = (const float*)d_in[1];
    const float* W     = (const float*)d_in[2];
    const float* a_src = (const float*)d_in[3];
    const float* a_dst = (const float*)d_in[4];
    float* out = (float*)d_out;

    k1_gemm<<<dim3(N_NODES / 64, F_OUT / 64), 256>>>(x, W);
    k2_logits<<<(N_NODES * H_HEADS) / 256, 256>>>(a_src, a_dst);
    k2b_pack<<<dim3(N_NODES / 32, C_OUT / 32), 256>>>();
    k3_agg<<<dim3(N_NODES / 64, 2, JSPLIT), 128>>>(adj);
    k4_final<<<(N_NODES * C_OUT / 4) / 256, 256>>>(out);
}

// round 14
// speedup vs baseline: 1.3806x; 1.0421x over previous
#include <cuda_runtime.h>
#include <cuda_bf16.h>
#include <cstdint>

// Problem constants
#define N_NODES 4096
#define F_IN    256
#define F_OUT   256
#define H_HEADS 4
#define D_HEAD  64
#define C_OUT   256

#define JSPLIT  8
#define JRANGE  (N_NODES / JSPLIT)   // 512 per CTA
#define NTILES  (JRANGE / 16)        // 32
#define NN16    (N_NODES / 16)       // 256

// ---------------- scratch (no cudaMalloc allowed) ----------------
__device__ __align__(16) float g_h  [N_NODES * F_OUT];
__device__ __align__(16) float g_S  [N_NODES * H_HEADS];      // [n*4+h]
__device__ __align__(16) float g_F1 [N_NODES * H_HEADS];
__device__ __align__(16) float g_F2 [N_NODES * H_HEADS];
__device__ __align__(16) float g_Tt [H_HEADS * N_NODES];      // [h][n]
__device__ __align__(16) float2 g_E12t[H_HEADS * N_NODES];    // [h][n] = {E1, E2}
// fragment-packed B (tf32): [h][j16][c8][lane] -> uint4{b(k=m), b(m+4), b(m+8), b(m+12)}
__device__ uint4 g_Bpk[H_HEADS * NN16 * 8 * 32];
__device__ __align__(16) float g_U [JSPLIT][N_NODES * C_OUT];
__device__ __align__(16) float g_Z [JSPLIT][N_NODES * H_HEADS];

// ---------------- mma.sync helpers ----------------
__device__ __forceinline__ void mma_tf32(float* c, const uint32_t* a,
                                         uint32_t b0, uint32_t b1) {
    asm volatile(
        "mma.sync.aligned.m16n8k8.row.col.f32.tf32.tf32.f32 "
        "{%0,%1,%2,%3}, {%4,%5,%6,%7}, {%8,%9}, {%0,%1,%2,%3};"
        : "+f"(c[0]), "+f"(c[1]), "+f"(c[2]), "+f"(c[3])
        : "r"(a[0]), "r"(a[1]), "r"(a[2]), "r"(a[3]), "r"(b0), "r"(b1));
}
__device__ __forceinline__ uint32_t f2tf32(float f) {
    uint32_t r;
    asm("cvt.rna.tf32.f32 %0, %1;" : "=r"(r) : "f"(f));
    return r;
}
__device__ __forceinline__ void cp16(uint32_t dst, const void* src) {
    asm volatile("cp.async.cg.shared.global [%0], [%1], 16;"
                 :: "r"(dst), "l"(src) : "memory");
}

// ================= K1: h = x @ W^T  (4096x256x256) =================
__global__ void __launch_bounds__(256) k1_gemm(const float* __restrict__ x,
                                               const float* __restrict__ W) {
    __shared__ float xs[16][68];
    __shared__ float ws[16][68];
    const int tid = threadIdx.x;
    const int m0 = blockIdx.x * 64;
    const int n0 = blockIdx.y * 64;
    const int tr = tid >> 4, tc = tid & 15;
    const int lm = tid >> 2, lk4 = (tid & 3) << 2;

    float acc[4][4];
#pragma unroll
    for (int r = 0; r < 4; r++)
#pragma unroll
        for (int c = 0; c < 4; c++) acc[r][c] = 0.f;

    for (int k0 = 0; k0 < F_IN; k0 += 16) {
        float4 xv = *(const float4*)(x + (size_t)(m0 + lm) * F_IN + k0 + lk4);
        float4 wv = *(const float4*)(W + (size_t)(n0 + lm) * F_IN + k0 + lk4);
        __syncthreads();
        xs[lk4 + 0][lm] = xv.x; xs[lk4 + 1][lm] = xv.y;
        xs[lk4 + 2][lm] = xv.z; xs[lk4 + 3][lm] = xv.w;
        ws[lk4 + 0][lm] = wv.x; ws[lk4 + 1][lm] = wv.y;
        ws[lk4 + 2][lm] = wv.z; ws[lk4 + 3][lm] = wv.w;
        __syncthreads();
#pragma unroll
        for (int kk = 0; kk < 16; kk++) {
            float xa[4], wb[4];
#pragma unroll
            for (int r = 0; r < 4; r++) xa[r] = xs[kk][tr * 4 + r];
#pragma unroll
            for (int c = 0; c < 4; c++) wb[c] = ws[kk][tc * 4 + c];
#pragma unroll
            for (int r = 0; r < 4; r++)
#pragma unroll
                for (int c = 0; c < 4; c++) acc[r][c] += xa[r] * wb[c];
        }
    }
#pragma unroll
    for (int r = 0; r < 4; r++)
        *(float4*)(g_h + (size_t)(m0 + tr * 4 + r) * F_OUT + n0 + tc * 4) =
            make_float4(acc[r][0], acc[r][1], acc[r][2], acc[r][3]);
}

// ============ K2: per-node logits + exp factor tables ============
__global__ void __launch_bounds__(256) k2_logits(const float* __restrict__ a_src,
                                                 const float* __restrict__ a_dst) {
    const int idx = blockIdx.x * 256 + threadIdx.x;
    const int n  = idx >> 2;
    const int hh = idx & 3;
    const float* hp = g_h + (size_t)n * C_OUT + hh * D_HEAD;
    const float* as = a_src + hh * D_HEAD;
    const float* ad = a_dst + hh * D_HEAD;
    float s = 0.f, t = 0.f;
#pragma unroll
    for (int d = 0; d < D_HEAD; d += 4) {
        float4 hv = *(const float4*)(hp + d);
        float4 av = *(const float4*)(as + d);
        float4 dv = *(const float4*)(ad + d);
        s += hv.x * av.x + hv.y * av.y + hv.z * av.z + hv.w * av.w;
        t += hv.x * dv.x + hv.y * dv.y + hv.z * dv.z + hv.w * dv.w;
    }
    g_S [idx] = s;
    g_F1[idx] = expf(s);
    g_F2[idx] = expf(0.2f * s);
    g_Tt  [hh * N_NODES + n] = t;
    g_E12t[hh * N_NODES + n] = make_float2(expf(t), expf(0.2f * t));
}

// ============ K2b: pack h -> tf32 fragment-order B tiles ============
// Output chunk (h, j16, c8): lane l holds uint4 of tf32 values at
// c = c8*8 + (l>>2), j = j16*16 + (l&3) + {0,4,8,12}   (m16n8k8 B layout).
__global__ void __launch_bounds__(256) k2b_pack() {
    __shared__ float ts[32][33];
    const int tid = threadIdx.x;
    const int tx = tid & 31, ty = tid >> 5;
    const int n0 = blockIdx.x * 32;   // j dimension (nodes)
    const int c0 = blockIdx.y * 32;   // feature dimension
#pragma unroll
    for (int k = 0; k < 4; k++)
        ts[ty + 8 * k][tx] = g_h[(size_t)(n0 + ty + 8 * k) * C_OUT + c0 + tx];
    __syncthreads();

    const int lane = tid & 31;
    const int m    = lane & 3;
    const int cr   = lane >> 2;
    const int c8l  = (tid >> 5) & 3;
    const int j16l = tid >> 7;
    const int jl   = j16l * 16 + m;
    const int cl   = c8l * 8 + cr;

    const uint32_t b0 = f2tf32(ts[jl][cl]);
    const uint32_t b1 = f2tf32(ts[jl + 4][cl]);
    const uint32_t b2 = f2tf32(ts[jl + 8][cl]);
    const uint32_t b3 = f2tf32(ts[jl + 12][cl]);

    const int cg  = c0 + cl;
    const int h   = cg >> 6;
    const int c8  = (cg & 63) >> 3;
    const int j16 = (n0 >> 4) + j16l;
    g_Bpk[((h * NN16 + j16) * 8 + c8) * 32 + lane] = make_uint4(b0, b1, b2, b3);
}

// ---- weight for one (i, j): factored-exp masked softmax term ----
__device__ __forceinline__ float gat_w(float S, float F1, float F2,
                                       float T, float E1, float E2,
                                       float a, float& Z) {
    const float t = S + T;
    const float p = (t >= 0.f) ? F1 * E1 : F2 * E2;
    Z += (a > 0.f) ? p : 0.f;
    return fmaxf(a, 0.f) * p;
}

#define ADJ_STRIDE 20   // floats per smem row (16 data + 4 pad; row*20 mod 32 distinct)

// ======= K3: fused masked-softmax + aggregation via TF32 mma.sync =======
// CTA: 128 thr / 4 warps = 64 rows x 128 cols (2 heads).
// adj AND B tiles double-buffered in smem via cp.async; one barrier per tile.
// Single-product TF32: 32 MMA instr/tile (vs 48 for split-bf16 3-product).
__global__ void __launch_bounds__(128, 3) k3_agg(const float* __restrict__ adj) {
    __shared__ float adj_s[2][64][ADJ_STRIDE];
    __shared__ uint4 b_s[2][2][8][32];   // [buf][head-in-pair][c8][lane]

    const int tid  = threadIdx.x;
    const int wid  = tid >> 5;
    const int lane = tid & 31;
    const int i0   = blockIdx.x * 64;
    const int hp   = blockIdx.y;
    const int js   = blockIdx.z;
    const int rg   = wid >> 1;                 // row group 0..1
    const int hw   = wid & 1;                  // head-in-pair for this warp
    const int h    = hp * 2 + hw;
    const int m    = lane & 3;
    const int rloc = rg * 32 + (lane >> 2);    // local row 0..63 (fragment row)
    const int rbase = i0 + rloc;
    const int jbeg  = js * JRANGE;

    // ---- staging roles ----
    const int srow = tid >> 1;
    const int scol = (tid & 1) * 8;
    const float* sgp = adj + (size_t)(i0 + srow) * N_NODES + jbeg + scol;
    const uint32_t adj_dst0 = (uint32_t)__cvta_generic_to_shared(&adj_s[0][srow][scol]);
    const uint32_t adj_buf_sz = (uint32_t)(64 * ADJ_STRIDE * 4);
    const uint4* bsrc[4];
#pragma unroll
    for (int k = 0; k < 4; k++) {
        const int idx = tid + k * 128;
        bsrc[k] = g_Bpk + ((size_t)(hp * 2 + (idx >> 8)) * NN16 + (jbeg >> 4)) * 256
                        + (idx & 255);
    }
    const uint32_t b_dst0 = (uint32_t)__cvta_generic_to_shared(&b_s[0][0][0][0]) + tid * 16;

    float S[4], F1[4], F2[4], Z[4];
#pragma unroll
    for (int r4 = 0; r4 < 4; r4++) {
        const int idx = (rbase + r4 * 8) * H_HEADS + h;
        S[r4] = g_S[idx]; F1[r4] = g_F1[idx]; F2[r4] = g_F2[idx];
        Z[r4] = 0.f;
    }
    const float*  Tp = g_Tt + h * N_NODES + jbeg;
    const float2* Ep = (const float2*)(g_E12t + h * N_NODES + jbeg);

    float acc[2][8][4];
#pragma unroll
    for (int mt = 0; mt < 2; mt++)
#pragma unroll
        for (int nt = 0; nt < 8; nt++)
#pragma unroll
            for (int q = 0; q < 4; q++) acc[mt][nt][q] = 0.f;

    // prologue: stage tile 0 into buf 0
    {
        cp16(adj_dst0, sgp);
        cp16(adj_dst0 + 16, sgp + 4);
#pragma unroll
        for (int k = 0; k < 4; k++) cp16(b_dst0 + k * 2048, bsrc[k]);
        asm volatile("cp.async.commit_group;" ::: "memory");
    }

#pragma unroll 1
    for (int t = 0; t < NTILES; t++) {
        const int buf = t & 1;
        const int jb  = t * 16;

        asm volatile("cp.async.wait_group 0;" ::: "memory");
        __syncthreads();   // tile t visible; all warps done reading buf^1

        // prefetch tile t+1 into buf^1 (overlaps with compute below)
        if (t + 1 < NTILES) {
            const uint32_t ad = adj_dst0 + (buf ^ 1) * adj_buf_sz;
            const float* gp = sgp + jb + 16;
            cp16(ad, gp);
            cp16(ad + 16, gp + 4);
            const uint32_t bd = b_dst0 + (buf ^ 1) * 8192;
#pragma unroll
            for (int k = 0; k < 4; k++)
                cp16(bd + k * 2048, bsrc[k] + (size_t)(t + 1) * 256);
            asm volatile("cp.async.commit_group;" ::: "memory");
        }

        // per-j tables for this lane's fragment k's: j = m, m+4, m+8, m+12
        const float T0 = Tp[jb + m],      T1 = Tp[jb + m + 4];
        const float T2 = Tp[jb + m + 8],  T3 = Tp[jb + m + 12];
        const float2 E0 = Ep[jb + m],     E1v = Ep[jb + m + 4];
        const float2 E2v = Ep[jb + m + 8], E3 = Ep[jb + m + 12];

        // weights directly in tf32 fragment layout from smem
        uint32_t A0[2][4], A1[2][4];   // k-chunk 0 (j m, m+4), chunk 1 (m+8, m+12)
#pragma unroll
        for (int r4 = 0; r4 < 4; r4++) {
            const float* arow = &adj_s[buf][rloc + r4 * 8][m];
            const float a0 = arow[0], a1 = arow[4], a2 = arow[8], a3 = arow[12];
            const float w0 = gat_w(S[r4], F1[r4], F2[r4], T0, E0.x,  E0.y,  a0, Z[r4]);
            const float w1 = gat_w(S[r4], F1[r4], F2[r4], T1, E1v.x, E1v.y, a1, Z[r4]);
            const float w2 = gat_w(S[r4], F1[r4], F2[r4], T2, E2v.x, E2v.y, a2, Z[r4]);
            const float w3 = gat_w(S[r4], F1[r4], F2[r4], T3, E3.x,  E3.y,  a3, Z[r4]);
            const int mt = r4 >> 1, hf = r4 & 1;
            A0[mt][hf]     = f2tf32(w0);
            A0[mt][2 + hf] = f2tf32(w1);
            A1[mt][hf]     = f2tf32(w2);
            A1[mt][2 + hf] = f2tf32(w3);
        }

        // B fragments from smem (LDS.128) + 2 k8 TF32 MMAs per (nt, mt)
#pragma unroll
        for (int nt = 0; nt < 8; nt++) {
            const uint4 bv = b_s[buf][hw][nt][lane];
#pragma unroll
            for (int mt = 0; mt < 2; mt++) {
                mma_tf32(acc[mt][nt], A0[mt], bv.x, bv.y);
                mma_tf32(acc[mt][nt], A1[mt], bv.z, bv.w);
            }
        }
    }

    // Z: reduce over the 4 lanes of each quad (disjoint j coverage)
#pragma unroll
    for (int r4 = 0; r4 < 4; r4++) {
        Z[r4] += __shfl_xor_sync(0xffffffffu, Z[r4], 1);
        Z[r4] += __shfl_xor_sync(0xffffffffu, Z[r4], 2);
    }
    if (m == 0) {
#pragma unroll
        for (int r4 = 0; r4 < 4; r4++)
            g_Z[js][(rbase + r4 * 8) * H_HEADS + h] = Z[r4];
    }

    // U partial store
#pragma unroll
    for (int mt = 0; mt < 2; mt++) {
        const int row_lo = i0 + rg * 32 + mt * 16 + (lane >> 2);
        const int row_hi = row_lo + 8;
#pragma unroll
        for (int nt = 0; nt < 8; nt++) {
            const int col = h * 64 + nt * 8 + 2 * m;
            *(float2*)(g_U[js] + (size_t)row_lo * C_OUT + col) =
                make_float2(acc[mt][nt][0], acc[mt][nt][1]);
            *(float2*)(g_U[js] + (size_t)row_hi * C_OUT + col) =
                make_float2(acc[mt][nt][2], acc[mt][nt][3]);
        }
    }
}

// ============ K4: reduce splits + normalize (+ nan_to_num) ============
__global__ void __launch_bounds__(256) k4_final(float* __restrict__ out) {
    const int idx = blockIdx.x * 256 + threadIdx.x;   // one float4 each
    const int n  = idx >> 6;
    const int c4 = (idx & 63) * 4;
    const int hh = c4 >> 6;
    float Z = 0.f;
#pragma unroll
    for (int s = 0; s < JSPLIT; s++) Z += g_Z[s][n * H_HEADS + hh];
    float4 u = make_float4(0.f, 0.f, 0.f, 0.f);
#pragma unroll
    for (int s = 0; s < JSPLIT; s++) {
        float4 v = *(const float4*)(g_U[s] + (size_t)n * C_OUT + c4);
        u.x += v.x; u.y += v.y; u.z += v.z; u.w += v.w;
    }
    const float r = (Z > 0.f) ? (1.f / Z) : 0.f;
    *(float4*)(out + (size_t)n * C_OUT + c4) =
        make_float4(u.x * r, u.y * r, u.z * r, u.w * r);
}

// ---------------- launch ----------------
extern "C" void kernel_launch(void* const* d_in, const int* in_sizes, int n_in,
                              void* d_out, int out_size) {
    const float* x     = (const float*)d_in[0];
    const float* adj   = (const float*)d_in[1];
    const float* W     = (const float*)d_in[2];
    const float* a_src = (const float*)d_in[3];
    const float* a_dst = (const float*)d_in[4];
    float* out = (float*)d_out;

    k1_gemm<<<dim3(N_NODES / 64, F_OUT / 64), 256>>>(x, W);
    k2_logits<<<(N_NODES * H_HEADS) / 256, 256>>>(a_src, a_dst);
    k2b_pack<<<dim3(N_NODES / 32, C_OUT / 32), 256>>>();
    k3_agg<<<dim3(N_NODES / 64, 2, JSPLIT), 128>>>(adj);
    k4_final<<<(N_NODES * C_OUT / 4) / 256, 256>>>(out);
}

// round 15
// speedup vs baseline: 1.5466x; 1.1202x over previous
#include <cuda_runtime.h>
#include <cuda_bf16.h>
#include <cstdint>

// Problem constants
#define N_NODES 4096
#define F_IN    256
#define F_OUT   256
#define H_HEADS 4
#define D_HEAD  64
#define C_OUT   256

#define JSPLIT  8
#define JRANGE  (N_NODES / JSPLIT)   // 512 per CTA
#define TJ      32                   // j per tile
#define NTILES  (JRANGE / TJ)        // 16
#define NN16    (N_NODES / 16)       // 256

// ---------------- scratch (no cudaMalloc allowed) ----------------
__device__ __align__(16) float g_h  [N_NODES * F_OUT];
__device__ __align__(16) float g_S  [N_NODES * H_HEADS];      // [n*4+h]
__device__ __align__(16) float g_F1 [N_NODES * H_HEADS];
__device__ __align__(16) float g_F2 [N_NODES * H_HEADS];
__device__ __align__(16) float g_Tt [H_HEADS * N_NODES];      // [h][n]
__device__ __align__(16) float2 g_E12t[H_HEADS * N_NODES];    // [h][n] = {E1, E2}
// fragment-packed B (tf32): [h][j16][c8][lane] -> uint4{b(k=m), b(m+4), b(m+8), b(m+12)}
__device__ uint4 g_Bpk[H_HEADS * NN16 * 8 * 32];
__device__ __align__(16) float g_U [JSPLIT][N_NODES * C_OUT];
__device__ __align__(16) float g_Z [JSPLIT][N_NODES * H_HEADS];

// ---------------- mma.sync helpers ----------------
__device__ __forceinline__ void mma_tf32(float* c, const uint32_t* a,
                                         uint32_t b0, uint32_t b1) {
    asm volatile(
        "mma.sync.aligned.m16n8k8.row.col.f32.tf32.tf32.f32 "
        "{%0,%1,%2,%3}, {%4,%5,%6,%7}, {%8,%9}, {%0,%1,%2,%3};"
        : "+f"(c[0]), "+f"(c[1]), "+f"(c[2]), "+f"(c[3])
        : "r"(a[0]), "r"(a[1]), "r"(a[2]), "r"(a[3]), "r"(b0), "r"(b1));
}
__device__ __forceinline__ uint32_t f2tf32(float f) {
    uint32_t r;
    asm("cvt.rna.tf32.f32 %0, %1;" : "=r"(r) : "f"(f));
    return r;
}
__device__ __forceinline__ void cp16(uint32_t dst, const void* src) {
    asm volatile("cp.async.cg.shared.global [%0], [%1], 16;"
                 :: "r"(dst), "l"(src) : "memory");
}

// ================= K1: h = x @ W^T  (4096x256x256) =================
__global__ void __launch_bounds__(256) k1_gemm(const float* __restrict__ x,
                                               const float* __restrict__ W) {
    __shared__ float xs[16][68];
    __shared__ float ws[16][68];
    const int tid = threadIdx.x;
    const int m0 = blockIdx.x * 64;
    const int n0 = blockIdx.y * 64;
    const int tr = tid >> 4, tc = tid & 15;
    const int lm = tid >> 2, lk4 = (tid & 3) << 2;

    float acc[4][4];
#pragma unroll
    for (int r = 0; r < 4; r++)
#pragma unroll
        for (int c = 0; c < 4; c++) acc[r][c] = 0.f;

    for (int k0 = 0; k0 < F_IN; k0 += 16) {
        float4 xv = *(const float4*)(x + (size_t)(m0 + lm) * F_IN + k0 + lk4);
        float4 wv = *(const float4*)(W + (size_t)(n0 + lm) * F_IN + k0 + lk4);
        __syncthreads();
        xs[lk4 + 0][lm] = xv.x; xs[lk4 + 1][lm] = xv.y;
        xs[lk4 + 2][lm] = xv.z; xs[lk4 + 3][lm] = xv.w;
        ws[lk4 + 0][lm] = wv.x; ws[lk4 + 1][lm] = wv.y;
        ws[lk4 + 2][lm] = wv.z; ws[lk4 + 3][lm] = wv.w;
        __syncthreads();
#pragma unroll
        for (int kk = 0; kk < 16; kk++) {
            float xa[4], wb[4];
#pragma unroll
            for (int r = 0; r < 4; r++) xa[r] = xs[kk][tr * 4 + r];
#pragma unroll
            for (int c = 0; c < 4; c++) wb[c] = ws[kk][tc * 4 + c];
#pragma unroll
            for (int r = 0; r < 4; r++)
#pragma unroll
                for (int c = 0; c < 4; c++) acc[r][c] += xa[r] * wb[c];
        }
    }
#pragma unroll
    for (int r = 0; r < 4; r++)
        *(float4*)(g_h + (size_t)(m0 + tr * 4 + r) * F_OUT + n0 + tc * 4) =
            make_float4(acc[r][0], acc[r][1], acc[r][2], acc[r][3]);
}

// ============ K2: per-node logits + exp factor tables ============
__global__ void __launch_bounds__(256) k2_logits(const float* __restrict__ a_src,
                                                 const float* __restrict__ a_dst) {
    const int idx = blockIdx.x * 256 + threadIdx.x;
    const int n  = idx >> 2;
    const int hh = idx & 3;
    const float* hp = g_h + (size_t)n * C_OUT + hh * D_HEAD;
    const float* as = a_src + hh * D_HEAD;
    const float* ad = a_dst + hh * D_HEAD;
    float s = 0.f, t = 0.f;
#pragma unroll
    for (int d = 0; d < D_HEAD; d += 4) {
        float4 hv = *(const float4*)(hp + d);
        float4 av = *(const float4*)(as + d);
        float4 dv = *(const float4*)(ad + d);
        s += hv.x * av.x + hv.y * av.y + hv.z * av.z + hv.w * av.w;
        t += hv.x * dv.x + hv.y * dv.y + hv.z * dv.z + hv.w * dv.w;
    }
    g_S [idx] = s;
    g_F1[idx] = expf(s);
    g_F2[idx] = expf(0.2f * s);
    g_Tt  [hh * N_NODES + n] = t;
    g_E12t[hh * N_NODES + n] = make_float2(expf(t), expf(0.2f * t));
}

// ============ K2b: pack h -> tf32 fragment-order B tiles ============
__global__ void __launch_bounds__(256) k2b_pack() {
    __shared__ float ts[32][33];
    const int tid = threadIdx.x;
    const int tx = tid & 31, ty = tid >> 5;
    const int n0 = blockIdx.x * 32;   // j dimension (nodes)
    const int c0 = blockIdx.y * 32;   // feature dimension
#pragma unroll
    for (int k = 0; k < 4; k++)
        ts[ty + 8 * k][tx] = g_h[(size_t)(n0 + ty + 8 * k) * C_OUT + c0 + tx];
    __syncthreads();

    const int lane = tid & 31;
    const int m    = lane & 3;
    const int cr   = lane >> 2;
    const int c8l  = (tid >> 5) & 3;
    const int j16l = tid >> 7;
    const int jl   = j16l * 16 + m;
    const int cl   = c8l * 8 + cr;

    const uint32_t b0 = f2tf32(ts[jl][cl]);
    const uint32_t b1 = f2tf32(ts[jl + 4][cl]);
    const uint32_t b2 = f2tf32(ts[jl + 8][cl]);
    const uint32_t b3 = f2tf32(ts[jl + 12][cl]);

    const int cg  = c0 + cl;
    const int h   = cg >> 6;
    const int c8  = (cg & 63) >> 3;
    const int j16 = (n0 >> 4) + j16l;
    g_Bpk[((h * NN16 + j16) * 8 + c8) * 32 + lane] = make_uint4(b0, b1, b2, b3);
}

// ---- weight for one (i, j): factored-exp masked softmax term ----
__device__ __forceinline__ float gat_w(float S, float F1, float F2,
                                       float T, float E1, float E2,
                                       float a, float& Z) {
    const float t = S + T;
    const float p = (t >= 0.f) ? F1 * E1 : F2 * E2;
    Z += (a > 0.f) ? p : 0.f;
    return fmaxf(a, 0.f) * p;
}

#define ADJ_STRIDE 36   // floats per smem row (32 data + 4 pad; row*36 mod 32 = row*4)

// ======= K3: fused masked-softmax + aggregation via TF32 mma.sync =======
// CTA: 256 thr / 8 warps = 64 rows x 128 cols (2 heads); warp = 16 rows x 64 cols.
// 32-j tiles double-buffered via cp.async; 2 CTAs/SM -> 4 warps/SMSP.
__global__ void __launch_bounds__(256, 2) k3_agg(const float* __restrict__ adj) {
    __shared__ float adj_s[2][64][ADJ_STRIDE];           // 18 KB
    __shared__ uint4 b_s[2][2][2][8][32];                // [buf][hw][j16sub][c8][lane] 32 KB

    const int tid  = threadIdx.x;
    const int wid  = tid >> 5;
    const int lane = tid & 31;
    const int i0   = blockIdx.x * 64;
    const int hp   = blockIdx.y;
    const int js   = blockIdx.z;
    const int rg   = wid >> 1;                 // row group 0..3 (16 rows each)
    const int hw   = wid & 1;                  // head-in-pair for this warp
    const int h    = hp * 2 + hw;
    const int m    = lane & 3;
    const int rloc = rg * 16 + (lane >> 2);    // local row 0..63 (fragment row)
    const int rbase = i0 + rloc;
    const int jbeg  = js * JRANGE;

    // ---- staging roles ----
    // adj: 64 rows x 32 floats = 512 x 16B chunks; thread stages 2 (d = tid + k*256)
    // B: 1024 x 16B chunks; thread stages 4
    const uint32_t adj_base = (uint32_t)__cvta_generic_to_shared(&adj_s[0][0][0]);
    const uint32_t b_base   = (uint32_t)__cvta_generic_to_shared(&b_s[0][0][0][0][0]);
    const float* asrc[2];
    uint32_t adst[2];
#pragma unroll
    for (int k = 0; k < 2; k++) {
        const int d = tid + k * 256;
        const int row = d >> 3, col4 = (d & 7) * 4;
        asrc[k] = adj + (size_t)(i0 + row) * N_NODES + jbeg + col4;
        adst[k] = adj_base + (row * ADJ_STRIDE + col4) * 4;
    }
    const uint4* bsrc[4];
#pragma unroll
    for (int k = 0; k < 4; k++) {
        const int d = tid + k * 256;
        const int hw_d = d >> 9, j16sub = (d >> 8) & 1, rest = d & 255;
        bsrc[k] = g_Bpk + ((size_t)(hp * 2 + hw_d) * NN16 + (jbeg >> 4) + j16sub) * 256 + rest;
    }
    const uint32_t b_dst0 = b_base + tid * 16;

    float S[2], F1[2], F2[2], Z[2];
#pragma unroll
    for (int r4 = 0; r4 < 2; r4++) {
        const int idx = (rbase + r4 * 8) * H_HEADS + h;
        S[r4] = g_S[idx]; F1[r4] = g_F1[idx]; F2[r4] = g_F2[idx];
        Z[r4] = 0.f;
    }
    const float*  Tp = g_Tt + h * N_NODES + jbeg;
    const float2* Ep = (const float2*)(g_E12t + h * N_NODES + jbeg);

    float acc[8][4];
#pragma unroll
    for (int nt = 0; nt < 8; nt++)
#pragma unroll
        for (int q = 0; q < 4; q++) acc[nt][q] = 0.f;

    // prologue: stage tile 0 into buf 0
    {
#pragma unroll
        for (int k = 0; k < 2; k++) cp16(adst[k], asrc[k]);
#pragma unroll
        for (int k = 0; k < 4; k++) cp16(b_dst0 + k * 4096, bsrc[k]);
        asm volatile("cp.async.commit_group;" ::: "memory");
    }

#pragma unroll 1
    for (int t = 0; t < NTILES; t++) {
        const int buf = t & 1;
        const int jb  = t * TJ;

        asm volatile("cp.async.wait_group 0;" ::: "memory");
        __syncthreads();   // tile t visible; all warps done reading buf^1

        // prefetch tile t+1 into buf^1 (overlaps with compute below)
        if (t + 1 < NTILES) {
            const uint32_t abuf = (buf ^ 1) * (uint32_t)(64 * ADJ_STRIDE * 4);
#pragma unroll
            for (int k = 0; k < 2; k++) cp16(adst[k] + abuf, asrc[k] + jb + TJ);
            const uint32_t bbuf = (buf ^ 1) * 16384u;
#pragma unroll
            for (int k = 0; k < 4; k++)
                cp16(b_dst0 + bbuf + k * 4096, bsrc[k] + (size_t)(t + 1) * 512);
            asm volatile("cp.async.commit_group;" ::: "memory");
        }

        // weights directly in tf32 fragment layout from smem
        // lane owns j = m + 4q, q = 0..7; rows rbase, rbase+8
        uint32_t A[4][4];
        const float* arow0 = &adj_s[buf][rloc][m];
        const float* arow1 = &adj_s[buf][rloc + 8][m];
#pragma unroll
        for (int q = 0; q < 8; q++) {
            const int j = m + 4 * q;
            const float Tq = Tp[jb + j];
            const float2 Eq = Ep[jb + j];
            const float a0 = arow0[4 * q];
            const float a1 = arow1[4 * q];
            const float w0 = gat_w(S[0], F1[0], F2[0], Tq, Eq.x, Eq.y, a0, Z[0]);
            const float w1 = gat_w(S[1], F1[1], F2[1], Tq, Eq.x, Eq.y, a1, Z[1]);
            const int chunk = q >> 1;
            const int sl = 2 * (q & 1);
            A[chunk][sl]     = f2tf32(w0);
            A[chunk][sl + 1] = f2tf32(w1);
        }

        // B fragments from smem (LDS.128) + TF32 MMAs: 32 per warp-tile
#pragma unroll
        for (int s = 0; s < 2; s++) {
#pragma unroll
            for (int nt = 0; nt < 8; nt++) {
                const uint4 bv = b_s[buf][hw][s][nt][lane];
                mma_tf32(acc[nt], A[2 * s],     bv.x, bv.y);
                mma_tf32(acc[nt], A[2 * s + 1], bv.z, bv.w);
            }
        }
    }

    // Z: reduce over the 4 lanes of each quad (disjoint j coverage)
#pragma unroll
    for (int r4 = 0; r4 < 2; r4++) {
        Z[r4] += __shfl_xor_sync(0xffffffffu, Z[r4], 1);
        Z[r4] += __shfl_xor_sync(0xffffffffu, Z[r4], 2);
    }
    if (m == 0) {
#pragma unroll
        for (int r4 = 0; r4 < 2; r4++)
            g_Z[js][(rbase + r4 * 8) * H_HEADS + h] = Z[r4];
    }

    // U partial store
    const int row_lo = rbase;
    const int row_hi = rbase + 8;
#pragma unroll
    for (int nt = 0; nt < 8; nt++) {
        const int col = h * 64 + nt * 8 + 2 * m;
        *(float2*)(g_U[js] + (size_t)row_lo * C_OUT + col) =
            make_float2(acc[nt][0], acc[nt][1]);
        *(float2*)(g_U[js] + (size_t)row_hi * C_OUT + col) =
            make_float2(acc[nt][2], acc[nt][3]);
    }
}

// ============ K4: reduce splits + normalize (+ nan_to_num) ============
__global__ void __launch_bounds__(256) k4_final(float* __restrict__ out) {
    const int idx = blockIdx.x * 256 + threadIdx.x;   // one float4 each
    const int n  = idx >> 6;
    const int c4 = (idx & 63) * 4;
    const int hh = c4 >> 6;
    float Z = 0.f;
#pragma unroll
    for (int s = 0; s < JSPLIT; s++) Z += g_Z[s][n * H_HEADS + hh];
    float4 u = make_float4(0.f, 0.f, 0.f, 0.f);
#pragma unroll
    for (int s = 0; s < JSPLIT; s++) {
        float4 v = *(const float4*)(g_U[s] + (size_t)n * C_OUT + c4);
        u.x += v.x; u.y += v.y; u.z += v.z; u.w += v.w;
    }
    const float r = (Z > 0.f) ? (1.f / Z) : 0.f;
    *(float4*)(out + (size_t)n * C_OUT + c4) =
        make_float4(u.x * r, u.y * r, u.z * r, u.w * r);
}

// ---------------- launch ----------------
extern "C" void kernel_launch(void* const* d_in, const int* in_sizes, int n_in,
                              void* d_out, int out_size) {
    const float* x     = (const float*)d_in[0];
    const float* adj   = (const float*)d_in[1];
    const float* W     = (const float*)d_in[2];
    const float* a_src = (const float*)d_in[3];
    const float* a_dst = (const float*)d_in[4];
    float* out = (float*)d_out;

    k1_gemm<<<dim3(N_NODES / 64, F_OUT / 64), 256>>>(x, W);
    k2_logits<<<(N_NODES * H_HEADS) / 256, 256>>>(a_src, a_dst);
    k2b_pack<<<dim3(N_NODES / 32, C_OUT / 32), 256>>>();
    k3_agg<<<dim3(N_NODES / 64, 2, JSPLIT), 256>>>(adj);
    k4_final<<<(N_NODES * C_OUT / 4) / 256, 256>>>(out);
}

// round 16
// speedup vs baseline: 1.7275x; 1.1170x over previous
#include <cuda_runtime.h>
#include <cuda_bf16.h>
#include <cstdint>

// Problem constants
#define N_NODES 4096
#define F_IN    256
#define F_OUT   256
#define H_HEADS 4
#define D_HEAD  64
#define C_OUT   256

#define JSPLIT  8
#define JRANGE  (N_NODES / JSPLIT)   // 512 per CTA
#define TJ      32                   // j per tile
#define NTILES  (JRANGE / TJ)        // 16
#define NN16    (N_NODES / 16)       // 256

// ---------------- scratch (no cudaMalloc allowed) ----------------
__device__ __align__(16) float g_h  [N_NODES * F_OUT];
__device__ __align__(16) float g_S  [N_NODES * H_HEADS];      // [n*4+h]
__device__ __align__(16) float g_F1 [N_NODES * H_HEADS];
__device__ __align__(16) float g_F2 [N_NODES * H_HEADS];
__device__ __align__(16) float g_Tt [H_HEADS * N_NODES];      // [h][n]
__device__ __align__(16) float2 g_E12t[H_HEADS * N_NODES];    // [h][n] = {E1, E2}
// fragment-packed B (tf32): [h][j16][c8][lane] -> uint4{b(k=m), b(m+4), b(m+8), b(m+12)}
__device__ uint4 g_Bpk[H_HEADS * NN16 * 8 * 32];
__device__ __align__(16) float g_U [JSPLIT][N_NODES * C_OUT];
__device__ __align__(16) float g_Z [JSPLIT][N_NODES * H_HEADS];

// ---------------- mma.sync helpers ----------------
__device__ __forceinline__ void mma_tf32(float* c, const uint32_t* a,
                                         uint32_t b0, uint32_t b1) {
    asm volatile(
        "mma.sync.aligned.m16n8k8.row.col.f32.tf32.tf32.f32 "
        "{%0,%1,%2,%3}, {%4,%5,%6,%7}, {%8,%9}, {%0,%1,%2,%3};"
        : "+f"(c[0]), "+f"(c[1]), "+f"(c[2]), "+f"(c[3])
        : "r"(a[0]), "r"(a[1]), "r"(a[2]), "r"(a[3]), "r"(b0), "r"(b1));
}
__device__ __forceinline__ uint32_t f2tf32(float f) {
    uint32_t r;
    asm("cvt.rna.tf32.f32 %0, %1;" : "=r"(r) : "f"(f));
    return r;
}
__device__ __forceinline__ void cp16(uint32_t dst, const void* src) {
    asm volatile("cp.async.cg.shared.global [%0], [%1], 16;"
                 :: "r"(dst), "l"(src) : "memory");
}

// ================= K1: h = x @ W^T via TF32 mma.sync =================
// CTA 64x64 tile, 128 thr / 4 warps; warp = 32 rows x 32 cols (mt=2, nt=4).
// K-loop: 16 steps of k16, cp.async double-buffered.
#define K1_PAD 20
__global__ void __launch_bounds__(128) k1_gemm(const float* __restrict__ x,
                                               const float* __restrict__ W) {
    __shared__ float As[2][64][K1_PAD];
    __shared__ float Bs[2][64][K1_PAD];
    const int tid = threadIdx.x;
    const int wid = tid >> 5, lane = tid & 31;
    const int m0 = blockIdx.x * 64, n0 = blockIdx.y * 64;
    const int rg = wid >> 1, cn = wid & 1;
    const int r4 = lane >> 2, m4 = lane & 3;

    const uint32_t aBase = (uint32_t)__cvta_generic_to_shared(&As[0][0][0]);
    const uint32_t bBase = (uint32_t)__cvta_generic_to_shared(&Bs[0][0][0]);
    const uint32_t bufSz = 64 * K1_PAD * 4;

    // staging: 256 16B chunks each for A and B; thread stages 2+2
    const float* asrc[2]; const float* bsrc[2];
    uint32_t adst[2], bdst[2];
#pragma unroll
    for (int k = 0; k < 2; k++) {
        const int d = tid + k * 128;
        const int row = d >> 2, c4 = (d & 3) * 4;
        asrc[k] = x + (size_t)(m0 + row) * F_IN + c4;
        bsrc[k] = W + (size_t)(n0 + row) * F_IN + c4;
        adst[k] = aBase + (row * K1_PAD + c4) * 4;
        bdst[k] = bBase + (row * K1_PAD + c4) * 4;
    }

    float acc[2][4][4];
#pragma unroll
    for (int mt = 0; mt < 2; mt++)
#pragma unroll
        for (int nt = 0; nt < 4; nt++)
#pragma unroll
            for (int q = 0; q < 4; q++) acc[mt][nt][q] = 0.f;

    // prologue: stage k-step 0
    {
#pragma unroll
        for (int k = 0; k < 2; k++) { cp16(adst[k], asrc[k]); cp16(bdst[k], bsrc[k]); }
        asm volatile("cp.async.commit_group;" ::: "memory");
    }

#pragma unroll 1
    for (int t = 0; t < F_IN / 16; t++) {
        const int buf = t & 1;
        asm volatile("cp.async.wait_group 0;" ::: "memory");
        __syncthreads();

        if (t + 1 < F_IN / 16) {
            const uint32_t off = (buf ^ 1) * bufSz;
            const int kk = (t + 1) * 16;
#pragma unroll
            for (int k = 0; k < 2; k++) {
                cp16(adst[k] + off, asrc[k] + kk);
                cp16(bdst[k] + off, bsrc[k] + kk);
            }
            asm volatile("cp.async.commit_group;" ::: "memory");
        }

#pragma unroll
        for (int c = 0; c < 2; c++) {
            const int kb = c * 8 + m4;
            uint32_t A[2][4], B[4][2];
#pragma unroll
            for (int mt = 0; mt < 2; mt++) {
                const int row = rg * 32 + mt * 16 + r4;
                A[mt][0] = f2tf32(As[buf][row][kb]);
                A[mt][1] = f2tf32(As[buf][row + 8][kb]);
                A[mt][2] = f2tf32(As[buf][row][kb + 4]);
                A[mt][3] = f2tf32(As[buf][row + 8][kb + 4]);
            }
#pragma unroll
            for (int nt = 0; nt < 4; nt++) {
                const int n = cn * 32 + nt * 8 + r4;
                B[nt][0] = f2tf32(Bs[buf][n][kb]);
                B[nt][1] = f2tf32(Bs[buf][n][kb + 4]);
            }
#pragma unroll
            for (int mt = 0; mt < 2; mt++)
#pragma unroll
                for (int nt = 0; nt < 4; nt++)
                    mma_tf32(acc[mt][nt], A[mt], B[nt][0], B[nt][1]);
        }
        __syncthreads();
    }

    // epilogue: write g_h
#pragma unroll
    for (int mt = 0; mt < 2; mt++) {
        const int row = m0 + rg * 32 + mt * 16 + r4;
#pragma unroll
        for (int nt = 0; nt < 4; nt++) {
            const int col = n0 + cn * 32 + nt * 8 + 2 * m4;
            *(float2*)(g_h + (size_t)row * F_OUT + col) =
                make_float2(acc[mt][nt][0], acc[mt][nt][1]);
            *(float2*)(g_h + (size_t)(row + 8) * F_OUT + col) =
                make_float2(acc[mt][nt][2], acc[mt][nt][3]);
        }
    }
}

// ============ K2: per-node logits + exp factor tables ============
__global__ void __launch_bounds__(256) k2_logits(const float* __restrict__ a_src,
                                                 const float* __restrict__ a_dst) {
    const int idx = blockIdx.x * 256 + threadIdx.x;
    const int n  = idx >> 2;
    const int hh = idx & 3;
    const float* hp = g_h + (size_t)n * C_OUT + hh * D_HEAD;
    const float* as = a_src + hh * D_HEAD;
    const float* ad = a_dst + hh * D_HEAD;
    float s = 0.f, t = 0.f;
#pragma unroll
    for (int d = 0; d < D_HEAD; d += 4) {
        float4 hv = *(const float4*)(hp + d);
        float4 av = *(const float4*)(as + d);
        float4 dv = *(const float4*)(ad + d);
        s += hv.x * av.x + hv.y * av.y + hv.z * av.z + hv.w * av.w;
        t += hv.x * dv.x + hv.y * dv.y + hv.z * dv.z + hv.w * dv.w;
    }
    g_S [idx] = s;
    g_F1[idx] = expf(s);
    g_F2[idx] = expf(0.2f * s);
    g_Tt  [hh * N_NODES + n] = t;
    g_E12t[hh * N_NODES + n] = make_float2(expf(t), expf(0.2f * t));
}

// ============ K2b: pack h -> tf32 fragment-order B tiles ============
__global__ void __launch_bounds__(256) k2b_pack() {
    __shared__ float ts[32][33];
    const int tid = threadIdx.x;
    const int tx = tid & 31, ty = tid >> 5;
    const int n0 = blockIdx.x * 32;   // j dimension (nodes)
    const int c0 = blockIdx.y * 32;   // feature dimension
#pragma unroll
    for (int k = 0; k < 4; k++)
        ts[ty + 8 * k][tx] = g_h[(size_t)(n0 + ty + 8 * k) * C_OUT + c0 + tx];
    __syncthreads();

    const int lane = tid & 31;
    const int m    = lane & 3;
    const int cr   = lane >> 2;
    const int c8l  = (tid >> 5) & 3;
    const int j16l = tid >> 7;
    const int jl   = j16l * 16 + m;
    const int cl   = c8l * 8 + cr;

    const uint32_t b0 = f2tf32(ts[jl][cl]);
    const uint32_t b1 = f2tf32(ts[jl + 4][cl]);
    const uint32_t b2 = f2tf32(ts[jl + 8][cl]);
    const uint32_t b3 = f2tf32(ts[jl + 12][cl]);

    const int cg  = c0 + cl;
    const int h   = cg >> 6;
    const int c8  = (cg & 63) >> 3;
    const int j16 = (n0 >> 4) + j16l;
    g_Bpk[((h * NN16 + j16) * 8 + c8) * 32 + lane] = make_uint4(b0, b1, b2, b3);
}

// ---- weight for one (i, j): factored-exp masked softmax term ----
__device__ __forceinline__ float gat_w(float S, float F1, float F2,
                                       float T, float E1, float E2,
                                       float a, float& Z) {
    const float t = S + T;
    const float p = (t >= 0.f) ? F1 * E1 : F2 * E2;
    Z += (a > 0.f) ? p : 0.f;
    return fmaxf(a, 0.f) * p;
}

#define ADJ_STRIDE 36   // floats per smem row (32 data + 4 pad; row*36 mod 32 = row*4)

// ======= K3: fused masked-softmax + aggregation via TF32 mma.sync =======
// CTA: 256 thr / 8 warps = 64 rows x 128 cols (2 heads); warp = 16 rows x 64 cols.
// 32-j tiles double-buffered via cp.async; T/E tables staged to smem once.
__global__ void __launch_bounds__(256, 2) k3_agg(const float* __restrict__ adj) {
    __shared__ float adj_s[2][64][ADJ_STRIDE];           // 18 KB
    __shared__ uint4 b_s[2][2][2][8][32];                // 32 KB
    __shared__ float  Ts_s[2][JRANGE];                   // 4 KB  (per-head T tables)
    __shared__ float2 Es_s[2][JRANGE];                   // 8 KB  (per-head {E1,E2})

    const int tid  = threadIdx.x;
    const int wid  = tid >> 5;
    const int lane = tid & 31;
    const int i0   = blockIdx.x * 64;
    const int hp   = blockIdx.y;
    const int js   = blockIdx.z;
    const int rg   = wid >> 1;                 // row group 0..3 (16 rows each)
    const int hw   = wid & 1;                  // head-in-pair for this warp
    const int h    = hp * 2 + hw;
    const int m    = lane & 3;
    const int rloc = rg * 16 + (lane >> 2);    // local row 0..63 (fragment row)
    const int rbase = i0 + rloc;
    const int jbeg  = js * JRANGE;

    // ---- staging roles ----
    const uint32_t adj_base = (uint32_t)__cvta_generic_to_shared(&adj_s[0][0][0]);
    const float* asrc[2];
    uint32_t adst[2];
#pragma unroll
    for (int k = 0; k < 2; k++) {
        const int d = tid + k * 256;
        const int row = d >> 3, col4 = (d & 7) * 4;
        asrc[k] = adj + (size_t)(i0 + row) * N_NODES + jbeg + col4;
        adst[k] = adj_base + (row * ADJ_STRIDE + col4) * 4;
    }
    const uint4* bsrc[4];
#pragma unroll
    for (int k = 0; k < 4; k++) {
        const int d = tid + k * 256;
        const int hw_d = d >> 9, j16sub = (d >> 8) & 1, rest = d & 255;
        bsrc[k] = g_Bpk + ((size_t)(hp * 2 + hw_d) * NN16 + (jbeg >> 4) + j16sub) * 256 + rest;
    }
    const uint32_t b_dst0 =
        (uint32_t)__cvta_generic_to_shared(&b_s[0][0][0][0][0]) + tid * 16;

    // one-time T/E table staging (covered by first mainloop __syncthreads)
#pragma unroll
    for (int k = 0; k < 4; k++) {
        const int d = tid + k * 256;          // 0..1023
        const int hh = d >> 9, j = d & 511;
        Ts_s[hh][j] = g_Tt[(size_t)(hp * 2 + hh) * N_NODES + jbeg + j];
        Es_s[hh][j] = g_E12t[(size_t)(hp * 2 + hh) * N_NODES + jbeg + j];
    }

    float S[2], F1[2], F2[2], Z[2];
#pragma unroll
    for (int r4 = 0; r4 < 2; r4++) {
        const int idx = (rbase + r4 * 8) * H_HEADS + h;
        S[r4] = g_S[idx]; F1[r4] = g_F1[idx]; F2[r4] = g_F2[idx];
        Z[r4] = 0.f;
    }

    float acc[8][4];
#pragma unroll
    for (int nt = 0; nt < 8; nt++)
#pragma unroll
        for (int q = 0; q < 4; q++) acc[nt][q] = 0.f;

    // prologue: stage tile 0 into buf 0
    {
#pragma unroll
        for (int k = 0; k < 2; k++) cp16(adst[k], asrc[k]);
#pragma unroll
        for (int k = 0; k < 4; k++) cp16(b_dst0 + k * 4096, bsrc[k]);
        asm volatile("cp.async.commit_group;" ::: "memory");
    }

#pragma unroll 1
    for (int t = 0; t < NTILES; t++) {
        const int buf = t & 1;
        const int jb  = t * TJ;

        asm volatile("cp.async.wait_group 0;" ::: "memory");
        __syncthreads();   // tile t (and prologue T/E staging) visible

        // prefetch tile t+1 into buf^1 (overlaps with compute below)
        if (t + 1 < NTILES) {
            const uint32_t abuf = (buf ^ 1) * (uint32_t)(64 * ADJ_STRIDE * 4);
#pragma unroll
            for (int k = 0; k < 2; k++) cp16(adst[k] + abuf, asrc[k] + jb + TJ);
            const uint32_t bbuf = (buf ^ 1) * 16384u;
#pragma unroll
            for (int k = 0; k < 4; k++)
                cp16(b_dst0 + bbuf + k * 4096, bsrc[k] + (size_t)(t + 1) * 512);
            asm volatile("cp.async.commit_group;" ::: "memory");
        }

        // weights directly in tf32 fragment layout from smem
        // lane owns j = m + 4q, q = 0..7; rows rbase, rbase+8
        uint32_t A[4][4];
        const float* arow0 = &adj_s[buf][rloc][m];
        const float* arow1 = &adj_s[buf][rloc + 8][m];
#pragma unroll
        for (int q = 0; q < 8; q++) {
            const int j = m + 4 * q;
            const float Tq = Ts_s[hw][jb + j];
            const float2 Eq = Es_s[hw][jb + j];
            const float a0 = arow0[4 * q];
            const float a1 = arow1[4 * q];
            const float w0 = gat_w(S[0], F1[0], F2[0], Tq, Eq.x, Eq.y, a0, Z[0]);
            const float w1 = gat_w(S[1], F1[1], F2[1], Tq, Eq.x, Eq.y, a1, Z[1]);
            const int chunk = q >> 1;
            const int sl = 2 * (q & 1);
            A[chunk][sl]     = f2tf32(w0);
            A[chunk][sl + 1] = f2tf32(w1);
        }

        // B fragments from smem (LDS.128) + TF32 MMAs: 32 per warp-tile
#pragma unroll
        for (int s = 0; s < 2; s++) {
#pragma unroll
            for (int nt = 0; nt < 8; nt++) {
                const uint4 bv = b_s[buf][hw][s][nt][lane];
                mma_tf32(acc[nt], A[2 * s],     bv.x, bv.y);
                mma_tf32(acc[nt], A[2 * s + 1], bv.z, bv.w);
            }
        }
    }

    // Z: reduce over the 4 lanes of each quad (disjoint j coverage)
#pragma unroll
    for (int r4 = 0; r4 < 2; r4++) {
        Z[r4] += __shfl_xor_sync(0xffffffffu, Z[r4], 1);
        Z[r4] += __shfl_xor_sync(0xffffffffu, Z[r4], 2);
    }
    if (m == 0) {
#pragma unroll
        for (int r4 = 0; r4 < 2; r4++)
            g_Z[js][(rbase + r4 * 8) * H_HEADS + h] = Z[r4];
    }

    // U partial store
    const int row_lo = rbase;
    const int row_hi = rbase + 8;
#pragma unroll
    for (int nt = 0; nt < 8; nt++) {
        const int col = h * 64 + nt * 8 + 2 * m;
        *(float2*)(g_U[js] + (size_t)row_lo * C_OUT + col) =
            make_float2(acc[nt][0], acc[nt][1]);
        *(float2*)(g_U[js] + (size_t)row_hi * C_OUT + col) =
            make_float2(acc[nt][2], acc[nt][3]);
    }
}

// ============ K4: reduce splits + normalize (+ nan_to_num) ============
__global__ void __launch_bounds__(256) k4_final(float* __restrict__ out) {
    const int idx = blockIdx.x * 256 + threadIdx.x;   // one float4 each
    const int n  = idx >> 6;
    const int c4 = (idx & 63) * 4;
    const int hh = c4 >> 6;
    float Z = 0.f;
#pragma unroll
    for (int s = 0; s < JSPLIT; s++) Z += g_Z[s][n * H_HEADS + hh];
    float4 u = make_float4(0.f, 0.f, 0.f, 0.f);
#pragma unroll
    for (int s = 0; s < JSPLIT; s++) {
        float4 v = *(const float4*)(g_U[s] + (size_t)n * C_OUT + c4);
        u.x += v.x; u.y += v.y; u.z += v.z; u.w += v.w;
    }
    const float r = (Z > 0.f) ? (1.f / Z) : 0.f;
    *(float4*)(out + (size_t)n * C_OUT + c4) =
        make_float4(u.x * r, u.y * r, u.z * r, u.w * r);
}

// ---------------- launch ----------------
extern "C" void kernel_launch(void* const* d_in, const int* in_sizes, int n_in,
                              void* d_out, int out_size) {
    const float* x     = (const float*)d_in[0];
    const float* adj   = (const float*)d_in[1];
    const float* W     = (const float*)d_in[2];
    const float* a_src = (const float*)d_in[3];
    const float* a_dst = (const float*)d_in[4];
    float* out = (float*)d_out;

    k1_gemm<<<dim3(N_NODES / 64, F_OUT / 64), 128>>>(x, W);
    k2_logits<<<(N_NODES * H_HEADS) / 256, 256>>>(a_src, a_dst);
    k2b_pack<<<dim3(N_NODES / 32, C_OUT / 32), 256>>>();
    k3_agg<<<dim3(N_NODES / 64, 2, JSPLIT), 256>>>(adj);
    k4_final<<<(N_NODES * C_OUT / 4) / 256, 256>>>(out);
}

// round 17
// speedup vs baseline: 1.7607x; 1.0192x over previous
#include <cuda_runtime.h>
#include <cuda_bf16.h>
#include <cstdint>

// Problem constants
#define N_NODES 4096
#define F_IN    256
#define F_OUT   256
#define H_HEADS 4
#define D_HEAD  64
#define C_OUT   256

#define JSPLIT  8
#define JRANGE  (N_NODES / JSPLIT)   // 512 per CTA
#define TJ      32                   // j per tile
#define NTILES  (JRANGE / TJ)        // 16
#define NN16    (N_NODES / 16)       // 256

// ---------------- scratch (no cudaMalloc allowed) ----------------
__device__ __align__(16) float g_h  [N_NODES * F_OUT];
__device__ __align__(16) float g_S  [N_NODES * H_HEADS];      // [n*4+h]
__device__ __align__(16) float g_F1 [N_NODES * H_HEADS];
__device__ __align__(16) float g_F2 [N_NODES * H_HEADS];
__device__ __align__(16) float g_Tt [H_HEADS * N_NODES];      // [h][n]
__device__ __align__(16) float2 g_E12t[H_HEADS * N_NODES];    // [h][n] = {E1, E2}
// fragment-packed B (tf32): [h][j16][c8][lane] -> uint4{b(k=m), b(m+4), b(m+8), b(m+12)}
__device__ uint4 g_Bpk[H_HEADS * NN16 * 8 * 32];
__device__ __align__(16) float g_U [JSPLIT][N_NODES * C_OUT];
__device__ __align__(16) float g_Z [JSPLIT][N_NODES * H_HEADS];

// ---------------- mma.sync helpers ----------------
__device__ __forceinline__ void mma_tf32(float* c, const uint32_t* a,
                                         uint32_t b0, uint32_t b1) {
    asm volatile(
        "mma.sync.aligned.m16n8k8.row.col.f32.tf32.tf32.f32 "
        "{%0,%1,%2,%3}, {%4,%5,%6,%7}, {%8,%9}, {%0,%1,%2,%3};"
        : "+f"(c[0]), "+f"(c[1]), "+f"(c[2]), "+f"(c[3])
        : "r"(a[0]), "r"(a[1]), "r"(a[2]), "r"(a[3]), "r"(b0), "r"(b1));
}
__device__ __forceinline__ uint32_t f2tf32(float f) {
    uint32_t r;
    asm("cvt.rna.tf32.f32 %0, %1;" : "=r"(r) : "f"(f));
    return r;
}
__device__ __forceinline__ void cp16(uint32_t dst, const void* src) {
    asm volatile("cp.async.cg.shared.global [%0], [%1], 16;"
                 :: "r"(dst), "l"(src) : "memory");
}

// ================= K1: h = x @ W^T via TF32 mma.sync =================
#define K1_PAD 20
__global__ void __launch_bounds__(128) k1_gemm(const float* __restrict__ x,
                                               const float* __restrict__ W) {
    __shared__ float As[2][64][K1_PAD];
    __shared__ float Bs[2][64][K1_PAD];
    const int tid = threadIdx.x;
    const int wid = tid >> 5, lane = tid & 31;
    const int m0 = blockIdx.x * 64, n0 = blockIdx.y * 64;
    const int rg = wid >> 1, cn = wid & 1;
    const int r4 = lane >> 2, m4 = lane & 3;

    const uint32_t aBase = (uint32_t)__cvta_generic_to_shared(&As[0][0][0]);
    const uint32_t bBase = (uint32_t)__cvta_generic_to_shared(&Bs[0][0][0]);
    const uint32_t bufSz = 64 * K1_PAD * 4;

    const float* asrc[2]; const float* bsrc[2];
    uint32_t adst[2], bdst[2];
#pragma unroll
    for (int k = 0; k < 2; k++) {
        const int d = tid + k * 128;
        const int row = d >> 2, c4 = (d & 3) * 4;
        asrc[k] = x + (size_t)(m0 + row) * F_IN + c4;
        bsrc[k] = W + (size_t)(n0 + row) * F_IN + c4;
        adst[k] = aBase + (row * K1_PAD + c4) * 4;
        bdst[k] = bBase + (row * K1_PAD + c4) * 4;
    }

    float acc[2][4][4];
#pragma unroll
    for (int mt = 0; mt < 2; mt++)
#pragma unroll
        for (int nt = 0; nt < 4; nt++)
#pragma unroll
            for (int q = 0; q < 4; q++) acc[mt][nt][q] = 0.f;

    {
#pragma unroll
        for (int k = 0; k < 2; k++) { cp16(adst[k], asrc[k]); cp16(bdst[k], bsrc[k]); }
        asm volatile("cp.async.commit_group;" ::: "memory");
    }

#pragma unroll 1
    for (int t = 0; t < F_IN / 16; t++) {
        const int buf = t & 1;
        asm volatile("cp.async.wait_group 0;" ::: "memory");
        __syncthreads();

        if (t + 1 < F_IN / 16) {
            const uint32_t off = (buf ^ 1) * bufSz;
            const int kk = (t + 1) * 16;
#pragma unroll
            for (int k = 0; k < 2; k++) {
                cp16(adst[k] + off, asrc[k] + kk);
                cp16(bdst[k] + off, bsrc[k] + kk);
            }
            asm volatile("cp.async.commit_group;" ::: "memory");
        }

#pragma unroll
        for (int c = 0; c < 2; c++) {
            const int kb = c * 8 + m4;
            uint32_t A[2][4], B[4][2];
#pragma unroll
            for (int mt = 0; mt < 2; mt++) {
                const int row = rg * 32 + mt * 16 + r4;
                A[mt][0] = f2tf32(As[buf][row][kb]);
                A[mt][1] = f2tf32(As[buf][row + 8][kb]);
                A[mt][2] = f2tf32(As[buf][row][kb + 4]);
                A[mt][3] = f2tf32(As[buf][row + 8][kb + 4]);
            }
#pragma unroll
            for (int nt = 0; nt < 4; nt++) {
                const int n = cn * 32 + nt * 8 + r4;
                B[nt][0] = f2tf32(Bs[buf][n][kb]);
                B[nt][1] = f2tf32(Bs[buf][n][kb + 4]);
            }
#pragma unroll
            for (int mt = 0; mt < 2; mt++)
#pragma unroll
                for (int nt = 0; nt < 4; nt++)
                    mma_tf32(acc[mt][nt], A[mt], B[nt][0], B[nt][1]);
        }
        __syncthreads();
    }

#pragma unroll
    for (int mt = 0; mt < 2; mt++) {
        const int row = m0 + rg * 32 + mt * 16 + r4;
#pragma unroll
        for (int nt = 0; nt < 4; nt++) {
            const int col = n0 + cn * 32 + nt * 8 + 2 * m4;
            *(float2*)(g_h + (size_t)row * F_OUT + col) =
                make_float2(acc[mt][nt][0], acc[mt][nt][1]);
            *(float2*)(g_h + (size_t)(row + 8) * F_OUT + col) =
                make_float2(acc[mt][nt][2], acc[mt][nt][3]);
        }
    }
}

// ============ K2: per-node logits + exp factor tables ============
__global__ void __launch_bounds__(256) k2_logits(const float* __restrict__ a_src,
                                                 const float* __restrict__ a_dst) {
    const int idx = blockIdx.x * 256 + threadIdx.x;
    const int n  = idx >> 2;
    const int hh = idx & 3;
    const float* hp = g_h + (size_t)n * C_OUT + hh * D_HEAD;
    const float* as = a_src + hh * D_HEAD;
    const float* ad = a_dst + hh * D_HEAD;
    float s = 0.f, t = 0.f;
#pragma unroll
    for (int d = 0; d < D_HEAD; d += 4) {
        float4 hv = *(const float4*)(hp + d);
        float4 av = *(const float4*)(as + d);
        float4 dv = *(const float4*)(ad + d);
        s += hv.x * av.x + hv.y * av.y + hv.z * av.z + hv.w * av.w;
        t += hv.x * dv.x + hv.y * dv.y + hv.z * dv.z + hv.w * dv.w;
    }
    g_S [idx] = s;
    g_F1[idx] = expf(s);
    g_F2[idx] = expf(0.2f * s);
    g_Tt  [hh * N_NODES + n] = t;
    g_E12t[hh * N_NODES + n] = make_float2(expf(t), expf(0.2f * t));
}

// ============ K2b: pack h -> tf32 fragment-order B tiles ============
__global__ void __launch_bounds__(256) k2b_pack() {
    __shared__ float ts[32][33];
    const int tid = threadIdx.x;
    const int tx = tid & 31, ty = tid >> 5;
    const int n0 = blockIdx.x * 32;   // j dimension (nodes)
    const int c0 = blockIdx.y * 32;   // feature dimension
#pragma unroll
    for (int k = 0; k < 4; k++)
        ts[ty + 8 * k][tx] = g_h[(size_t)(n0 + ty + 8 * k) * C_OUT + c0 + tx];
    __syncthreads();

    const int lane = tid & 31;
    const int m    = lane & 3;
    const int cr   = lane >> 2;
    const int c8l  = (tid >> 5) & 3;
    const int j16l = tid >> 7;
    const int jl   = j16l * 16 + m;
    const int cl   = c8l * 8 + cr;

    const uint32_t b0 = f2tf32(ts[jl][cl]);
    const uint32_t b1 = f2tf32(ts[jl + 4][cl]);
    const uint32_t b2 = f2tf32(ts[jl + 8][cl]);
    const uint32_t b3 = f2tf32(ts[jl + 12][cl]);

    const int cg  = c0 + cl;
    const int h   = cg >> 6;
    const int c8  = (cg & 63) >> 3;
    const int j16 = (n0 >> 4) + j16l;
    g_Bpk[((h * NN16 + j16) * 8 + c8) * 32 + lane] = make_uint4(b0, b1, b2, b3);
}

// ---- weight for one (i, j): factored-exp masked softmax term ----
__device__ __forceinline__ float gat_w(float S, float F1, float F2,
                                       float T, float E1, float E2,
                                       float a, float& Z) {
    const float t = S + T;
    const float p = (t >= 0.f) ? F1 * E1 : F2 * E2;
    Z += (a > 0.f) ? p : 0.f;
    return fmaxf(a, 0.f) * p;
}

#define ADJ_STRIDE 36   // floats per smem row (32 data + 4 pad; row*36 mod 32 = row*4)
#define ADJ_BUF_SZ (64 * ADJ_STRIDE * 4)

// ======= K3: fused masked-softmax + aggregation via TF32 mma.sync =======
// Per-HEAD CTA: 128 thr / 4 warps = 64 rows x 64 cols (1 head); warp 16x64.
// 40 KB smem, <=128 regs -> 4 CTAs/SM (4 independent barrier domains).
__global__ void __launch_bounds__(128, 4) k3_agg(const float* __restrict__ adj) {
    __shared__ float adj_s[2][64][ADJ_STRIDE];           // 18 KB
    __shared__ uint4 b_s[2][2][8][32];                   // [buf][j16sub][c8][lane] 16 KB
    __shared__ float  Ts_s[JRANGE];                      // 2 KB
    __shared__ float2 Es_s[JRANGE];                      // 4 KB

    const int tid  = threadIdx.x;
    const int wid  = tid >> 5;
    const int lane = tid & 31;
    const int i0   = blockIdx.x * 64;
    const int h    = blockIdx.y;
    const int js   = blockIdx.z;
    const int rg   = wid;                      // row group 0..3 (16 rows each)
    const int m    = lane & 3;
    const int rloc = rg * 16 + (lane >> 2);    // local row 0..63 (fragment row)
    const int rbase = i0 + rloc;
    const int jbeg  = js * JRANGE;

    const uint32_t adj_base = (uint32_t)__cvta_generic_to_shared(&adj_s[0][0][0]);
    const uint32_t b_base   = (uint32_t)__cvta_generic_to_shared(&b_s[0][0][0][0]);

    // staging geometry (recomputed per use; cheap ALU)
    const int srow0 = tid >> 3;                // adj rows srow0 + 16k
    const int scol4 = (tid & 7) * 4;
    const float* adj_row0 = adj + (size_t)(i0 + srow0) * N_NODES + jbeg + scol4;
    const uint4* bpk_base = g_Bpk + ((size_t)h * NN16 + (jbeg >> 4)) * 256;

    // one-time T/E table staging (visible after first mainloop barrier)
#pragma unroll
    for (int k = 0; k < 4; k++) {
        const int d = tid + k * 128;
        Ts_s[d] = g_Tt[(size_t)h * N_NODES + jbeg + d];
        Es_s[d] = g_E12t[(size_t)h * N_NODES + jbeg + d];
    }

    float S[2], F1[2], F2[2], Z[2];
#pragma unroll
    for (int r4 = 0; r4 < 2; r4++) {
        const int idx = (rbase + r4 * 8) * H_HEADS + h;
        S[r4] = g_S[idx]; F1[r4] = g_F1[idx]; F2[r4] = g_F2[idx];
        Z[r4] = 0.f;
    }

    float acc[8][4];
#pragma unroll
    for (int nt = 0; nt < 8; nt++)
#pragma unroll
        for (int q = 0; q < 4; q++) acc[nt][q] = 0.f;

    // prologue: stage tile 0 into buf 0
    {
#pragma unroll
        for (int k = 0; k < 4; k++)
            cp16(adj_base + ((srow0 + 16 * k) * ADJ_STRIDE + scol4) * 4,
                 adj_row0 + (size_t)(16 * k) * N_NODES);
#pragma unroll
        for (int k = 0; k < 4; k++) {
            const int sub = k >> 1, off = tid + (k & 1) * 128;
            cp16(b_base + sub * 4096 + off * 16, bpk_base + sub * 256 + off);
        }
        asm volatile("cp.async.commit_group;" ::: "memory");
    }

#pragma unroll 1
    for (int t = 0; t < NTILES; t++) {
        const int buf = t & 1;
        const int jb  = t * TJ;

        asm volatile("cp.async.wait_group 0;" ::: "memory");
        __syncthreads();   // tile t (and prologue T/E staging) visible

        // prefetch tile t+1 into buf^1 (overlaps with compute below)
        if (t + 1 < NTILES) {
            const uint32_t abuf = adj_base + (buf ^ 1) * ADJ_BUF_SZ;
#pragma unroll
            for (int k = 0; k < 4; k++)
                cp16(abuf + ((srow0 + 16 * k) * ADJ_STRIDE + scol4) * 4,
                     adj_row0 + (size_t)(16 * k) * N_NODES + jb + TJ);
            const uint32_t bbuf = b_base + (buf ^ 1) * 8192;
#pragma unroll
            for (int k = 0; k < 4; k++) {
                const int sub = k >> 1, off = tid + (k & 1) * 128;
                cp16(bbuf + sub * 4096 + off * 16,
                     bpk_base + (size_t)(2 * (t + 1) + sub) * 256 + off);
            }
            asm volatile("cp.async.commit_group;" ::: "memory");
        }

        // weights directly in tf32 fragment layout from smem
        uint32_t A[4][4];
        const float* arow0 = &adj_s[buf][rloc][m];
        const float* arow1 = &adj_s[buf][rloc + 8][m];
#pragma unroll
        for (int q = 0; q < 8; q++) {
            const int j = m + 4 * q;
            const float Tq = Ts_s[jb + j];
            const float2 Eq = Es_s[jb + j];
            const float a0 = arow0[4 * q];
            const float a1 = arow1[4 * q];
            const float w0 = gat_w(S[0], F1[0], F2[0], Tq, Eq.x, Eq.y, a0, Z[0]);
            const float w1 = gat_w(S[1], F1[1], F2[1], Tq, Eq.x, Eq.y, a1, Z[1]);
            const int chunk = q >> 1;
            const int sl = 2 * (q & 1);
            A[chunk][sl]     = f2tf32(w0);
            A[chunk][sl + 1] = f2tf32(w1);
        }

        // B fragments from smem (LDS.128) + TF32 MMAs: 32 per warp-tile
#pragma unroll
        for (int s = 0; s < 2; s++) {
#pragma unroll
            for (int nt = 0; nt < 8; nt++) {
                const uint4 bv = b_s[buf][s][nt][lane];
                mma_tf32(acc[nt], A[2 * s],     bv.x, bv.y);
                mma_tf32(acc[nt], A[2 * s + 1], bv.z, bv.w);
            }
        }
    }

    // Z: reduce over the 4 lanes of each quad (disjoint j coverage)
#pragma unroll
    for (int r4 = 0; r4 < 2; r4++) {
        Z[r4] += __shfl_xor_sync(0xffffffffu, Z[r4], 1);
        Z[r4] += __shfl_xor_sync(0xffffffffu, Z[r4], 2);
    }
    if (m == 0) {
#pragma unroll
        for (int r4 = 0; r4 < 2; r4++)
            g_Z[js][(rbase + r4 * 8) * H_HEADS + h] = Z[r4];
    }

    // U partial store
#pragma unroll
    for (int nt = 0; nt < 8; nt++) {
        const int col = h * 64 + nt * 8 + 2 * m;
        *(float2*)(g_U[js] + (size_t)rbase * C_OUT + col) =
            make_float2(acc[nt][0], acc[nt][1]);
        *(float2*)(g_U[js] + (size_t)(rbase + 8) * C_OUT + col) =
            make_float2(acc[nt][2], acc[nt][3]);
    }
}

// ============ K4: reduce splits + normalize (+ nan_to_num) ============
__global__ void __launch_bounds__(256) k4_final(float* __restrict__ out) {
    const int idx = blockIdx.x * 256 + threadIdx.x;   // one float4 each
    const int n  = idx >> 6;
    const int c4 = (idx & 63) * 4;
    const int hh = c4 >> 6;
    float Z = 0.f;
#pragma unroll
    for (int s = 0; s < JSPLIT; s++) Z += g_Z[s][n * H_HEADS + hh];
    float4 u = make_float4(0.f, 0.f, 0.f, 0.f);
#pragma unroll
    for (int s = 0; s < JSPLIT; s++) {
        float4 v = *(const float4*)(g_U[s] + (size_t)n * C_OUT + c4);
        u.x += v.x; u.y += v.y; u.z += v.z; u.w += v.w;
    }
    const float r = (Z > 0.f) ? (1.f / Z) : 0.f;
    *(float4*)(out + (size_t)n * C_OUT + c4) =
        make_float4(u.x * r, u.y * r, u.z * r, u.w * r);
}

// ---------------- launch ----------------
extern "C" void kernel_launch(void* const* d_in, const int* in_sizes, int n_in,
                              void* d_out, int out_size) {
    const float* x     = (const float*)d_in[0];
    const float* adj   = (const float*)d_in[1];
    const float* W     = (const float*)d_in[2];
    const float* a_src = (const float*)d_in[3];
    const float* a_dst = (const float*)d_in[4];
    float* out = (float*)d_out;

    k1_gemm<<<dim3(N_NODES / 64, F_OUT / 64), 128>>>(x, W);
    k2_logits<<<(N_NODES * H_HEADS) / 256, 256>>>(a_src, a_dst);
    k2b_pack<<<dim3(N_NODES / 32, C_OUT / 32), 256>>>();
    k3_agg<<<dim3(N_NODES / 64, H_HEADS, JSPLIT), 128>>>(adj);
    k4_final<<<(N_NODES * C_OUT / 4) / 256, 256>>>(out);
}